// round 1
// baseline (speedup 1.0000x reference)
#include <cuda_runtime.h>
#include <math.h>

#define NN    8192
#define KK    32
#define EE    (NN*KK)      // 262144 edges
#define CIN   128
#define CATT  128
#define NROWS 9            // (LMAX+1)^2
#define RAD3  768
#define FCO   256
#define EPB   16           // edges per block in k2

// ---- scratch (__device__ globals: allocation-free) ----
__device__ float g_node[(size_t)NN * NROWS * CATT];        // 37.7 MB
__device__ float g_y[(size_t)RAD3 * EE];                   // 805 MB, layout (768, E)

// ===================== K1: node_feat = node @ dot_w[l]^T (+bias l=0) ==========
__global__ void k1_node(const float* __restrict__ node_in,
                        const float* __restrict__ dot_w,
                        const float* __restrict__ dot_b) {
    __shared__ __align__(16) float sm[NROWS * CIN];
    int n = blockIdx.x;
    const float* src = node_in + (size_t)n * NROWS * CIN;
    for (int i = threadIdx.x; i < NROWS * CIN; i += blockDim.x) sm[i] = src[i];
    __syncthreads();
    for (int idx = threadIdx.x; idx < NROWS * CATT; idx += blockDim.x) {
        int m = idx >> 7;
        int d = idx & 127;
        int l = (m == 0) ? 0 : (m < 4 ? 1 : 2);
        const float4* w = reinterpret_cast<const float4*>(dot_w + (size_t)l * CATT * CIN + (size_t)d * CIN);
        const float4* x = reinterpret_cast<const float4*>(sm + m * CIN);
        float acc = (m == 0) ? dot_b[d] : 0.f;
#pragma unroll
        for (int c4 = 0; c4 < CIN / 4; c4++) {
            float4 wv = __ldg(&w[c4]);
            float4 xv = x[c4];
            acc += wv.x * xv.x + wv.y * xv.y + wv.z * xv.z + wv.w * xv.w;
        }
        g_node[(size_t)n * NROWS * CATT + idx] = acc;
    }
}

// ===================== K2: per-edge fused (SH, rad MLP, x0*edge_m0 -> g_y) ====
// smem strides
#define XS_STR 132
#define GN_STR 1154
#define H_STR  68

__device__ __forceinline__ void ln_silu_row(float* h, const float* __restrict__ g,
                                            const float* __restrict__ b) {
    float s1 = 0.f, s2 = 0.f;
    for (int c = 0; c < 64; c++) { float v = h[c]; s1 += v; s2 += v * v; }
    float mean = s1 * (1.f / 64.f);
    float var  = s2 * (1.f / 64.f) - mean * mean;
    float rs   = rsqrtf(var + 1e-5f);
    for (int c = 0; c < 64; c++) {
        float z = (h[c] - mean) * rs * g[c] + b[c];
        float sg = 1.f / (1.f + expf(-z));
        h[c] = z * sg;
    }
}

__global__ void __launch_bounds__(256, 2) k2_edge(
    const float* __restrict__ x_edge, const float* __restrict__ edge_vec,
    const int* __restrict__ sp_idx,
    const float* __restrict__ w0, const float* __restrict__ b0,
    const float* __restrict__ w1, const float* __restrict__ b1,
    const float* __restrict__ w2, const float* __restrict__ b2,
    const float* __restrict__ g0, const float* __restrict__ bb0,
    const float* __restrict__ g1, const float* __restrict__ bb1)
{
    extern __shared__ float smem[];
    float* xs  = smem;                      // EPB*132
    float* nf  = xs  + EPB * XS_STR;        // 1152
    float* gn  = nf  + NROWS * CATT;        // EPB*1154
    float* shs = gn  + EPB * GN_STR;        // EPB*12
    float* h0s = shs + EPB * 12;            // EPB*68
    float* h1s = h0s + EPB * H_STR;         // EPB*68
    int*   idxs = (int*)(h1s + EPB * H_STR);// EPB

    int tid  = threadIdx.x;
    int n    = blockIdx.y;
    int half = blockIdx.x;
    int kbase = half * EPB;

    if (tid < EPB) idxs[tid] = sp_idx[(size_t)n * KK + kbase + tid];

    // stage node_feat of n
    for (int i = tid; i < NROWS * CATT; i += 256)
        nf[i] = g_node[(size_t)n * NROWS * CATT + i];

    // stage x_edge rows
    for (int i = tid; i < EPB * CIN; i += 256) {
        int e = i >> 7, c = i & 127;
        xs[e * XS_STR + c] = x_edge[((size_t)(n * KK + kbase + e)) * CIN + c];
    }

    // spherical harmonics per edge
    if (tid < EPB) {
        const float* ev = edge_vec + ((size_t)(n * KK + kbase + tid)) * 3;
        float x = ev[0], y = ev[1], z = ev[2];
        float nrm = sqrtf(x * x + y * y + z * z);
        float inv = 1.f / fmaxf(nrm, 1e-12f);
        x *= inv; y *= inv; z *= inv;
        float* s = shs + tid * 12;
        const float C0 = 0.28209479177387814f;
        const float C1 = 0.4886025119029199f;
        const float C2 = 0.6307831305050401f;
        const float S3 = 1.7320508075688772f;
        s[0] = C0;
        s[1] = C1 * x; s[2] = C1 * y; s[3] = C1 * z;
        s[4] = C2 * S3 * x * z;
        s[5] = C2 * S3 * x * y;
        s[6] = C2 * (y * y - 0.5f * (x * x + z * z));
        s[7] = C2 * S3 * y * z;
        s[8] = C2 * 0.5f * S3 * (z * z - x * x);
    }
    __syncthreads();

    // stage gathered node_feat rows (coalesced)
    for (int i = tid; i < EPB * NROWS * CATT; i += 256) {
        int e = i / (NROWS * CATT);
        int r = i - e * (NROWS * CATT);
        gn[e * GN_STR + r] = g_node[(size_t)idxs[e] * (NROWS * CATT) + r];
    }

    int e      = tid & 15;
    int lane16 = tid >> 4;

    // rad layer 0: 128 -> 64
    {
        const float4* xr = reinterpret_cast<const float4*>(xs + e * XS_STR);
#pragma unroll
        for (int r = 0; r < 4; r++) {
            int o = lane16 + 16 * r;
            float acc = b0[o];
            const float4* w = reinterpret_cast<const float4*>(w0 + (size_t)o * 128);
#pragma unroll
            for (int c4 = 0; c4 < 32; c4++) {
                float4 wv = __ldg(&w[c4]);
                float4 xv = xr[c4];
                acc += wv.x * xv.x + wv.y * xv.y + wv.z * xv.z + wv.w * xv.w;
            }
            h0s[e * H_STR + o] = acc;
        }
    }
    __syncthreads();
    if (tid < EPB) ln_silu_row(h0s + tid * H_STR, g0, bb0);
    __syncthreads();

    // rad layer 1: 64 -> 64
    {
        const float4* hr = reinterpret_cast<const float4*>(h0s + e * H_STR);
#pragma unroll
        for (int r = 0; r < 4; r++) {
            int o = lane16 + 16 * r;
            float acc = b1[o];
            const float4* w = reinterpret_cast<const float4*>(w1 + (size_t)o * 64);
#pragma unroll
            for (int c4 = 0; c4 < 16; c4++) {
                float4 wv = __ldg(&w[c4]);
                float4 hv = hr[c4];
                acc += wv.x * hv.x + wv.y * hv.y + wv.z * hv.z + wv.w * hv.w;
            }
            h1s[e * H_STR + o] = acc;
        }
    }
    __syncthreads();
    if (tid < EPB) ln_silu_row(h1s + tid * H_STR, g1, bb1);
    __syncthreads();

    // h1 -> registers
    float h1r[64];
    {
        const float4* hr = reinterpret_cast<const float4*>(h1s + e * H_STR);
#pragma unroll
        for (int c4 = 0; c4 < 16; c4++) {
            float4 v = hr[c4];
            h1r[c4 * 4 + 0] = v.x; h1r[c4 * 4 + 1] = v.y;
            h1r[c4 * 4 + 2] = v.z; h1r[c4 * 4 + 3] = v.w;
        }
    }
    float shv[9];
#pragma unroll
    for (int m = 0; m < 9; m++) shv[m] = shs[e * 12 + m];
    const float* gne = gn + e * GN_STR;
    size_t eg = (size_t)n * KK + kbase + e;

    // main loop: edge_m0[j] = h1 . w2[j] + b2[j];  y[j] = x0[j] * edge_m0[j]
    for (int b = 0; b < 6; b++) {
#pragma unroll 4
        for (int jj0 = 0; jj0 < 128; jj0 += 16) {
            int d = jj0 + lane16;
            int j = b * 128 + d;
            float acc = b2[j];
            const float4* w = reinterpret_cast<const float4*>(w2 + (size_t)j * 64);
#pragma unroll
            for (int c4 = 0; c4 < 16; c4++) {
                float4 wv = __ldg(&w[c4]);
                acc += wv.x * h1r[c4 * 4] + wv.y * h1r[c4 * 4 + 1] +
                       wv.z * h1r[c4 * 4 + 2] + wv.w * h1r[c4 * 4 + 3];
            }
            float x0;
            if      (b == 0) x0 = shv[0] * nf[d];
            else if (b == 1) x0 = shv[0] * gne[d];
            else if (b == 2) x0 = shv[1] * nf[128 + d] + shv[2] * nf[256 + d] + shv[3] * nf[384 + d];
            else if (b == 3) x0 = shv[1] * gne[128 + d] + shv[2] * gne[256 + d] + shv[3] * gne[384 + d];
            else if (b == 4) x0 = shv[4] * nf[512 + d] + shv[5] * nf[640 + d] + shv[6] * nf[768 + d]
                                + shv[7] * nf[896 + d] + shv[8] * nf[1024 + d];
            else             x0 = shv[4] * gne[512 + d] + shv[5] * gne[640 + d] + shv[6] * gne[768 + d]
                                + shv[7] * gne[896 + d] + shv[8] * gne[1024 + d];
            g_y[(size_t)j * EE + eg] = x0 * acc;
        }
    }
}

// ===================== K3: (E x 768) @ fc_w^T (768 x 256) + LN/SLR/alpha =====
__global__ void __launch_bounds__(256) k3_gemm(
    const float* __restrict__ fc_w, const float* __restrict__ fc_b,
    const float* __restrict__ ln_g, const float* __restrict__ ln_b,
    const float* __restrict__ alpha_dot, float* __restrict__ out)
{
    __shared__ __align__(16) float As[16 * 132];
    __shared__ __align__(16) float Bs[16 * 128];
    int tid = threadIdx.x;
    int m0 = blockIdx.x * 128;
    int n0 = blockIdx.y * 128;
    int tx = tid & 15, ty = tid >> 4;

    float acc[8][8];
#pragma unroll
    for (int i = 0; i < 8; i++)
#pragma unroll
        for (int j = 0; j < 8; j++) acc[i][j] = 0.f;

    for (int k0 = 0; k0 < 768; k0 += 16) {
#pragma unroll
        for (int r = 0; r < 2; r++) {
            int id = tid + 256 * r;
            int kk = id >> 5;
            int mq = (id & 31) << 2;
            float4 v = *reinterpret_cast<const float4*>(&g_y[(size_t)(k0 + kk) * EE + m0 + mq]);
            *reinterpret_cast<float4*>(&As[kk * 132 + mq]) = v;
        }
#pragma unroll
        for (int r = 0; r < 2; r++) {
            int id = tid + 256 * r;
            int o  = id & 127;
            int kq = (id >> 7) << 2;
            float4 v = __ldg(reinterpret_cast<const float4*>(&fc_w[(size_t)(n0 + o) * 768 + k0 + kq]));
            Bs[(kq + 0) * 128 + o] = v.x;
            Bs[(kq + 1) * 128 + o] = v.y;
            Bs[(kq + 2) * 128 + o] = v.z;
            Bs[(kq + 3) * 128 + o] = v.w;
        }
        __syncthreads();
#pragma unroll
        for (int kk = 0; kk < 16; kk++) {
            float a[8], bv[8];
            *(float4*)&a[0]  = *(float4*)&As[kk * 132 + ty * 8];
            *(float4*)&a[4]  = *(float4*)&As[kk * 132 + ty * 8 + 4];
            *(float4*)&bv[0] = *(float4*)&Bs[kk * 128 + tx * 8];
            *(float4*)&bv[4] = *(float4*)&Bs[kk * 128 + tx * 8 + 4];
#pragma unroll
            for (int i = 0; i < 8; i++)
#pragma unroll
                for (int j = 0; j < 8; j++)
                    acc[i][j] += a[i] * bv[j];
        }
        __syncthreads();
    }

    // epilogue: bias, per-head LN(32), smooth-leaky-relu, alpha dot
    int h  = tx >> 2;                 // local head 0..3
    int hg = blockIdx.y * 4 + h;      // global head
    int dbase = (tx & 3) * 8;

    float lg[8], lb[8], ad[8], bias[8];
#pragma unroll
    for (int j = 0; j < 8; j++) {
        int d = dbase + j;
        lg[j]   = __ldg(&ln_g[d]);
        lb[j]   = __ldg(&ln_b[d]);
        ad[j]   = __ldg(&alpha_dot[hg * 32 + d]);
        bias[j] = __ldg(&fc_b[n0 + tx * 8 + j]);
    }
#pragma unroll
    for (int i = 0; i < 8; i++) {
        float s1 = 0.f, s2 = 0.f;
#pragma unroll
        for (int j = 0; j < 8; j++) {
            acc[i][j] += bias[j];
            s1 += acc[i][j];
            s2 += acc[i][j] * acc[i][j];
        }
        s1 += __shfl_xor_sync(0xffffffff, s1, 1);
        s2 += __shfl_xor_sync(0xffffffff, s2, 1);
        s1 += __shfl_xor_sync(0xffffffff, s1, 2);
        s2 += __shfl_xor_sync(0xffffffff, s2, 2);
        float mean = s1 * (1.f / 32.f);
        float var  = s2 * (1.f / 32.f) - mean * mean;
        float rs   = rsqrtf(var + 1e-5f);
        float p = 0.f;
#pragma unroll
        for (int j = 0; j < 8; j++) {
            float z = (acc[i][j] - mean) * rs * lg[j] + lb[j];
            float sg = 1.f / (1.f + expf(-z));
            float slr = 0.6f * z + 0.4f * z * (2.f * sg - 1.f);
            p += slr * ad[j];
        }
        p += __shfl_xor_sync(0xffffffff, p, 1);
        p += __shfl_xor_sync(0xffffffff, p, 2);
        if ((tx & 3) == 0)
            out[(size_t)(m0 + ty * 8 + i) * 8 + hg] = p;
    }
}

// ===================== launch =====================
extern "C" void kernel_launch(void* const* d_in, const int* in_sizes, int n_in,
                              void* d_out, int out_size) {
    const float* x_edge   = (const float*)d_in[0];
    const float* node_in  = (const float*)d_in[1];
    const float* edge_vec = (const float*)d_in[2];
    const int*   sp       = (const int*)d_in[3];
    const float* dot_w    = (const float*)d_in[4];
    const float* dot_b    = (const float*)d_in[5];
    const float* w0  = (const float*)d_in[6];
    const float* b0  = (const float*)d_in[7];
    const float* w1  = (const float*)d_in[8];
    const float* b1  = (const float*)d_in[9];
    const float* w2  = (const float*)d_in[10];
    const float* b2  = (const float*)d_in[11];
    const float* g0  = (const float*)d_in[12];
    const float* bb0 = (const float*)d_in[13];
    const float* g1  = (const float*)d_in[14];
    const float* bb1 = (const float*)d_in[15];
    const float* fcw = (const float*)d_in[16];
    const float* fcb = (const float*)d_in[17];
    const float* lng = (const float*)d_in[18];
    const float* lnb = (const float*)d_in[19];
    const float* ad  = (const float*)d_in[20];
    float* out = (float*)d_out;

    k1_node<<<NN, 256>>>(node_in, dot_w, dot_b);

    size_t smem2 = (size_t)(EPB * XS_STR + NROWS * CATT + EPB * GN_STR + EPB * 12 +
                            EPB * H_STR + EPB * H_STR + EPB) * sizeof(float);
    cudaFuncSetAttribute(k2_edge, cudaFuncAttributeMaxDynamicSharedMemorySize, (int)smem2);
    dim3 g2(KK / EPB, NN);
    k2_edge<<<g2, 256, smem2>>>(x_edge, edge_vec, sp,
                                w0, b0, w1, b1, w2, b2, g0, bb0, g1, bb1);

    dim3 g3(EE / 128, 2);
    k3_gemm<<<g3, 256>>>(fcw, fcb, lng, lnb, ad, out);
}

// round 3
// speedup vs baseline: 1.1443x; 1.1443x over previous
#include <cuda_runtime.h>
#include <cuda_bf16.h>
#include <math.h>
#include <stdint.h>

#define NN    8192
#define KK    32
#define EE    (NN*KK)      // 262144 edges
#define CIN   128
#define CATT  128
#define NROWS 9            // (LMAX+1)^2
#define RAD3  768
#define FCO   256
#define EPB   16           // edges per block in k2

// ---- scratch (__device__ globals: allocation-free) ----
__device__ float g_node[(size_t)NN * NROWS * CATT];        // 37.7 MB
__device__ float g_y[(size_t)RAD3 * EE];                   // 805 MB, layout (768, E)

// ===================== K1: node_feat = node @ dot_w[l]^T (+bias l=0) ==========
__global__ void k1_node(const float* __restrict__ node_in,
                        const float* __restrict__ dot_w,
                        const float* __restrict__ dot_b) {
    __shared__ __align__(16) float sm[NROWS * CIN];
    int n = blockIdx.x;
    const float* src = node_in + (size_t)n * NROWS * CIN;
    for (int i = threadIdx.x; i < NROWS * CIN; i += blockDim.x) sm[i] = src[i];
    __syncthreads();
    for (int idx = threadIdx.x; idx < NROWS * CATT; idx += blockDim.x) {
        int m = idx >> 7;
        int d = idx & 127;
        int l = (m == 0) ? 0 : (m < 4 ? 1 : 2);
        const float4* w = reinterpret_cast<const float4*>(dot_w + (size_t)l * CATT * CIN + (size_t)d * CIN);
        const float4* x = reinterpret_cast<const float4*>(sm + m * CIN);
        float acc = (m == 0) ? dot_b[d] : 0.f;
#pragma unroll
        for (int c4 = 0; c4 < CIN / 4; c4++) {
            float4 wv = __ldg(&w[c4]);
            float4 xv = x[c4];
            acc += wv.x * xv.x + wv.y * xv.y + wv.z * xv.z + wv.w * xv.w;
        }
        g_node[(size_t)n * NROWS * CATT + idx] = acc;
    }
}

// ===================== K2: per-edge fused (SH, rad MLP, x0*edge_m0 -> g_y) ====
#define XS_STR 132
#define GN_STR 1154
#define H_STR  68

__device__ __forceinline__ void ln_silu_row(float* h, const float* __restrict__ g,
                                            const float* __restrict__ b) {
    float s1 = 0.f, s2 = 0.f;
    for (int c = 0; c < 64; c++) { float v = h[c]; s1 += v; s2 += v * v; }
    float mean = s1 * (1.f / 64.f);
    float var  = s2 * (1.f / 64.f) - mean * mean;
    float rs   = rsqrtf(var + 1e-5f);
    for (int c = 0; c < 64; c++) {
        float z = (h[c] - mean) * rs * g[c] + b[c];
        float sg = 1.f / (1.f + expf(-z));
        h[c] = z * sg;
    }
}

__global__ void __launch_bounds__(256, 2) k2_edge(
    const float* __restrict__ x_edge, const float* __restrict__ edge_vec,
    const int* __restrict__ sp_idx,
    const float* __restrict__ w0, const float* __restrict__ b0,
    const float* __restrict__ w1, const float* __restrict__ b1,
    const float* __restrict__ w2, const float* __restrict__ b2,
    const float* __restrict__ g0, const float* __restrict__ bb0,
    const float* __restrict__ g1, const float* __restrict__ bb1)
{
    extern __shared__ float smem[];
    float* xs  = smem;                      // EPB*132
    float* nf  = xs  + EPB * XS_STR;        // 1152
    float* gn  = nf  + NROWS * CATT;        // EPB*1154
    float* shs = gn  + EPB * GN_STR;        // EPB*12
    float* h0s = shs + EPB * 12;            // EPB*68
    float* h1s = h0s + EPB * H_STR;         // EPB*68
    int*   idxs = (int*)(h1s + EPB * H_STR);// EPB

    int tid  = threadIdx.x;
    int n    = blockIdx.y;
    int half = blockIdx.x;
    int kbase = half * EPB;

    if (tid < EPB) idxs[tid] = sp_idx[(size_t)n * KK + kbase + tid];

    for (int i = tid; i < NROWS * CATT; i += 256)
        nf[i] = g_node[(size_t)n * NROWS * CATT + i];

    for (int i = tid; i < EPB * CIN; i += 256) {
        int e = i >> 7, c = i & 127;
        xs[e * XS_STR + c] = x_edge[((size_t)(n * KK + kbase + e)) * CIN + c];
    }

    if (tid < EPB) {
        const float* ev = edge_vec + ((size_t)(n * KK + kbase + tid)) * 3;
        float x = ev[0], y = ev[1], z = ev[2];
        float nrm = sqrtf(x * x + y * y + z * z);
        float inv = 1.f / fmaxf(nrm, 1e-12f);
        x *= inv; y *= inv; z *= inv;
        float* s = shs + tid * 12;
        const float C0 = 0.28209479177387814f;
        const float C1 = 0.4886025119029199f;
        const float C2 = 0.6307831305050401f;
        const float S3 = 1.7320508075688772f;
        s[0] = C0;
        s[1] = C1 * x; s[2] = C1 * y; s[3] = C1 * z;
        s[4] = C2 * S3 * x * z;
        s[5] = C2 * S3 * x * y;
        s[6] = C2 * (y * y - 0.5f * (x * x + z * z));
        s[7] = C2 * S3 * y * z;
        s[8] = C2 * 0.5f * S3 * (z * z - x * x);
    }
    __syncthreads();

    for (int i = tid; i < EPB * NROWS * CATT; i += 256) {
        int e = i / (NROWS * CATT);
        int r = i - e * (NROWS * CATT);
        gn[e * GN_STR + r] = g_node[(size_t)idxs[e] * (NROWS * CATT) + r];
    }

    int e      = tid & 15;
    int lane16 = tid >> 4;

    // rad layer 0: 128 -> 64
    {
        const float4* xr = reinterpret_cast<const float4*>(xs + e * XS_STR);
#pragma unroll
        for (int r = 0; r < 4; r++) {
            int o = lane16 + 16 * r;
            float acc = b0[o];
            const float4* w = reinterpret_cast<const float4*>(w0 + (size_t)o * 128);
#pragma unroll
            for (int c4 = 0; c4 < 32; c4++) {
                float4 wv = __ldg(&w[c4]);
                float4 xv = xr[c4];
                acc += wv.x * xv.x + wv.y * xv.y + wv.z * xv.z + wv.w * xv.w;
            }
            h0s[e * H_STR + o] = acc;
        }
    }
    __syncthreads();
    if (tid < EPB) ln_silu_row(h0s + tid * H_STR, g0, bb0);
    __syncthreads();

    // rad layer 1: 64 -> 64
    {
        const float4* hr = reinterpret_cast<const float4*>(h0s + e * H_STR);
#pragma unroll
        for (int r = 0; r < 4; r++) {
            int o = lane16 + 16 * r;
            float acc = b1[o];
            const float4* w = reinterpret_cast<const float4*>(w1 + (size_t)o * 64);
#pragma unroll
            for (int c4 = 0; c4 < 16; c4++) {
                float4 wv = __ldg(&w[c4]);
                float4 hv = hr[c4];
                acc += wv.x * hv.x + wv.y * hv.y + wv.z * hv.z + wv.w * hv.w;
            }
            h1s[e * H_STR + o] = acc;
        }
    }
    __syncthreads();
    if (tid < EPB) ln_silu_row(h1s + tid * H_STR, g1, bb1);
    __syncthreads();

    float h1r[64];
    {
        const float4* hr = reinterpret_cast<const float4*>(h1s + e * H_STR);
#pragma unroll
        for (int c4 = 0; c4 < 16; c4++) {
            float4 v = hr[c4];
            h1r[c4 * 4 + 0] = v.x; h1r[c4 * 4 + 1] = v.y;
            h1r[c4 * 4 + 2] = v.z; h1r[c4 * 4 + 3] = v.w;
        }
    }
    float shv[9];
#pragma unroll
    for (int m = 0; m < 9; m++) shv[m] = shs[e * 12 + m];
    const float* gne = gn + e * GN_STR;
    size_t eg = (size_t)n * KK + kbase + e;

    for (int b = 0; b < 6; b++) {
#pragma unroll 4
        for (int jj0 = 0; jj0 < 128; jj0 += 16) {
            int d = jj0 + lane16;
            int j = b * 128 + d;
            float acc = b2[j];
            const float4* w = reinterpret_cast<const float4*>(w2 + (size_t)j * 64);
#pragma unroll
            for (int c4 = 0; c4 < 16; c4++) {
                float4 wv = __ldg(&w[c4]);
                acc += wv.x * h1r[c4 * 4] + wv.y * h1r[c4 * 4 + 1] +
                       wv.z * h1r[c4 * 4 + 2] + wv.w * h1r[c4 * 4 + 3];
            }
            float x0;
            if      (b == 0) x0 = shv[0] * nf[d];
            else if (b == 1) x0 = shv[0] * gne[d];
            else if (b == 2) x0 = shv[1] * nf[128 + d] + shv[2] * nf[256 + d] + shv[3] * nf[384 + d];
            else if (b == 3) x0 = shv[1] * gne[128 + d] + shv[2] * gne[256 + d] + shv[3] * gne[384 + d];
            else if (b == 4) x0 = shv[4] * nf[512 + d] + shv[5] * nf[640 + d] + shv[6] * nf[768 + d]
                                + shv[7] * nf[896 + d] + shv[8] * nf[1024 + d];
            else             x0 = shv[4] * gne[512 + d] + shv[5] * gne[640 + d] + shv[6] * gne[768 + d]
                                + shv[7] * gne[896 + d] + shv[8] * gne[1024 + d];
            g_y[(size_t)j * EE + eg] = x0 * acc;
        }
    }
}

// ===================== K3: tensor-core GEMM (bf16 split) + LN/SLR/alpha ======
// C[m,n] = sum_k y[m,k] * fc_w[n,k], m = edge, 768 k, 256 n.
// A staged K-major (as stored) -> ldmatrix.trans; B staged [n][k] -> ldmatrix (non-trans).

#define A_STR 136   // bf16 elems per k-row (128 + 8 pad)  -> 272B, conflict-free
#define B_STR 40    // bf16 elems per n-row (32 + 8 pad)   -> 80B,  conflict-free

__device__ __forceinline__ uint32_t sptr(const void* p) {
    return (uint32_t)__cvta_generic_to_shared(p);
}

__device__ __forceinline__ void ldmx4_t(uint32_t addr, uint32_t& r0, uint32_t& r1,
                                        uint32_t& r2, uint32_t& r3) {
    asm volatile("ldmatrix.sync.aligned.m8n8.x4.trans.shared.b16 {%0,%1,%2,%3}, [%4];"
                 : "=r"(r0), "=r"(r1), "=r"(r2), "=r"(r3) : "r"(addr));
}

__device__ __forceinline__ void ldmx4(uint32_t addr, uint32_t& r0, uint32_t& r1,
                                      uint32_t& r2, uint32_t& r3) {
    asm volatile("ldmatrix.sync.aligned.m8n8.x4.shared.b16 {%0,%1,%2,%3}, [%4];"
                 : "=r"(r0), "=r"(r1), "=r"(r2), "=r"(r3) : "r"(addr));
}

__device__ __forceinline__ void mma16816(float* c, const uint32_t* a, const uint32_t* b) {
    asm volatile("mma.sync.aligned.m16n8k16.row.col.f32.bf16.bf16.f32 "
                 "{%0,%1,%2,%3}, {%4,%5,%6,%7}, {%8,%9}, {%0,%1,%2,%3};"
                 : "+f"(c[0]), "+f"(c[1]), "+f"(c[2]), "+f"(c[3])
                 : "r"(a[0]), "r"(a[1]), "r"(a[2]), "r"(a[3]), "r"(b[0]), "r"(b[1]));
}

__device__ __forceinline__ void split_bf16(float v, __nv_bfloat16& hi, __nv_bfloat16& lo) {
    hi = __float2bfloat16(v);
    lo = __float2bfloat16(v - __bfloat162float(hi));
}

__global__ void __launch_bounds__(256) k3_gemm(
    const float* __restrict__ fc_w, const float* __restrict__ fc_b,
    const float* __restrict__ ln_g, const float* __restrict__ ln_b,
    const float* __restrict__ alpha_dot, float* __restrict__ out)
{
    __shared__ __align__(16) __nv_bfloat16 Ahi[32 * A_STR];
    __shared__ __align__(16) __nv_bfloat16 Alo[32 * A_STR];
    __shared__ __align__(16) __nv_bfloat16 Bhi[128 * B_STR];
    __shared__ __align__(16) __nv_bfloat16 Blo[128 * B_STR];

    int tid  = threadIdx.x;
    int lane = tid & 31;
    int warp = tid >> 5;
    int warp_m = warp >> 1;          // 0..3 -> 32 rows each
    int warp_n = warp & 1;           // 0..1 -> 64 cols each
    int m0  = blockIdx.x * 128;
    int n0g = blockIdx.y * 128;

    float acc[2][8][4];
#pragma unroll
    for (int i = 0; i < 2; i++)
#pragma unroll
        for (int f = 0; f < 8; f++)
#pragma unroll
            for (int j = 0; j < 4; j++) acc[i][f][j] = 0.f;

    // ldmatrix lane address components
    int g = lane >> 3, r = lane & 7;
    int a_k  = r + ((g >> 1) << 3);          // A(trans): k within 16-step
    int a_e  = ((g & 1) << 3);               // A(trans): +0/+8 within m16
    int b_n  = r + ((g >> 1) << 3);          // B(non-trans): n within 16
    int b_k  = ((g & 1) << 3);               // B(non-trans): +0/+8 within k16

    for (int k0 = 0; k0 < 768; k0 += 32) {
        // ---- stage A (32k x 128e) fp32 -> bf16 hi/lo ----
#pragma unroll
        for (int p = 0; p < 4; p++) {
            int krow = (tid >> 5) + p * 8;
            int e4   = (tid & 31) * 4;
            float4 v = *reinterpret_cast<const float4*>(&g_y[(size_t)(k0 + krow) * EE + m0 + e4]);
            __nv_bfloat16 h0,h1,h2,h3,l0,l1,l2,l3;
            split_bf16(v.x, h0, l0); split_bf16(v.y, h1, l1);
            split_bf16(v.z, h2, l2); split_bf16(v.w, h3, l3);
            __nv_bfloat162* dh = reinterpret_cast<__nv_bfloat162*>(&Ahi[krow * A_STR + e4]);
            __nv_bfloat162* dl = reinterpret_cast<__nv_bfloat162*>(&Alo[krow * A_STR + e4]);
            dh[0] = __nv_bfloat162(h0, h1); dh[1] = __nv_bfloat162(h2, h3);
            dl[0] = __nv_bfloat162(l0, l1); dl[1] = __nv_bfloat162(l2, l3);
        }
        // ---- stage B (128n x 32k) ----
#pragma unroll
        for (int p = 0; p < 4; p++) {
            int nrow = (tid >> 3) + p * 32;
            int k4   = (tid & 7) * 4;
            float4 v = __ldg(reinterpret_cast<const float4*>(&fc_w[(size_t)(n0g + nrow) * 768 + k0 + k4]));
            __nv_bfloat16 h0,h1,h2,h3,l0,l1,l2,l3;
            split_bf16(v.x, h0, l0); split_bf16(v.y, h1, l1);
            split_bf16(v.z, h2, l2); split_bf16(v.w, h3, l3);
            __nv_bfloat162* dh = reinterpret_cast<__nv_bfloat162*>(&Bhi[nrow * B_STR + k4]);
            __nv_bfloat162* dl = reinterpret_cast<__nv_bfloat162*>(&Blo[nrow * B_STR + k4]);
            dh[0] = __nv_bfloat162(h0, h1); dh[1] = __nv_bfloat162(h2, h3);
            dl[0] = __nv_bfloat162(l0, l1); dl[1] = __nv_bfloat162(l2, l3);
        }
        __syncthreads();

#pragma unroll
        for (int kh = 0; kh < 2; kh++) {
            uint32_t ah[2][4], al[2][4];
#pragma unroll
            for (int mf = 0; mf < 2; mf++) {
                int e0 = warp_m * 32 + mf * 16;
                uint32_t ad_hi = sptr(&Ahi[(kh * 16 + a_k) * A_STR + e0 + a_e]);
                uint32_t ad_lo = sptr(&Alo[(kh * 16 + a_k) * A_STR + e0 + a_e]);
                ldmx4_t(ad_hi, ah[mf][0], ah[mf][1], ah[mf][2], ah[mf][3]);
                ldmx4_t(ad_lo, al[mf][0], al[mf][1], al[mf][2], al[mf][3]);
            }
#pragma unroll
            for (int np = 0; np < 4; np++) {
                int nb = warp_n * 64 + np * 16;
                uint32_t bh[4], bl[4];
                uint32_t bd_hi = sptr(&Bhi[(nb + b_n) * B_STR + kh * 16 + b_k]);
                uint32_t bd_lo = sptr(&Blo[(nb + b_n) * B_STR + kh * 16 + b_k]);
                ldmx4(bd_hi, bh[0], bh[1], bh[2], bh[3]);
                ldmx4(bd_lo, bl[0], bl[1], bl[2], bl[3]);
#pragma unroll
                for (int mf = 0; mf < 2; mf++) {
#pragma unroll
                    for (int half8 = 0; half8 < 2; half8++) {
                        float* c = acc[mf][2 * np + half8];
                        mma16816(c, ah[mf], &bh[half8 * 2]);
                        mma16816(c, al[mf], &bh[half8 * 2]);
                        mma16816(c, ah[mf], &bl[half8 * 2]);
                    }
                }
            }
        }
        __syncthreads();
    }

    // ---- epilogue: bias, per-head LN(32), smooth-leaky, alpha dot ----
    int q = lane & 3;                 // quad position = col group
    float lg[2][8], lb[2][8], ad[2][8], bias[2][8];
#pragma unroll
    for (int h = 0; h < 2; h++) {
        int hg = blockIdx.y * 4 + warp_n * 2 + h;
#pragma unroll
        for (int fq = 0; fq < 4; fq++) {
#pragma unroll
            for (int j = 0; j < 2; j++) {
                int d   = fq * 8 + q * 2 + j;             // 0..31 within head
                int col = n0g + warp_n * 64 + h * 32 + d; // global col
                lg[h][fq * 2 + j]   = __ldg(&ln_g[d]);
                lb[h][fq * 2 + j]   = __ldg(&ln_b[d]);
                ad[h][fq * 2 + j]   = __ldg(&alpha_dot[hg * 32 + d]);
                bias[h][fq * 2 + j] = __ldg(&fc_b[col]);
            }
        }
    }

#pragma unroll
    for (int mf = 0; mf < 2; mf++) {
#pragma unroll
        for (int half8 = 0; half8 < 2; half8++) {
            int row = m0 + warp_m * 32 + mf * 16 + (lane >> 2) + half8 * 8;
#pragma unroll
            for (int h = 0; h < 2; h++) {
                float v[8];
#pragma unroll
                for (int fq = 0; fq < 4; fq++) {
                    int f = 4 * h + fq;
                    v[fq * 2 + 0] = acc[mf][f][half8 * 2 + 0] + bias[h][fq * 2 + 0];
                    v[fq * 2 + 1] = acc[mf][f][half8 * 2 + 1] + bias[h][fq * 2 + 1];
                }
                float s1 = 0.f, s2 = 0.f;
#pragma unroll
                for (int j = 0; j < 8; j++) { s1 += v[j]; s2 += v[j] * v[j]; }
                s1 += __shfl_xor_sync(0xffffffff, s1, 1);
                s2 += __shfl_xor_sync(0xffffffff, s2, 1);
                s1 += __shfl_xor_sync(0xffffffff, s1, 2);
                s2 += __shfl_xor_sync(0xffffffff, s2, 2);
                float mean = s1 * (1.f / 32.f);
                float var  = s2 * (1.f / 32.f) - mean * mean;
                float rs   = rsqrtf(var + 1e-5f);
                float p = 0.f;
#pragma unroll
                for (int j = 0; j < 8; j++) {
                    float z = (v[j] - mean) * rs * lg[h][j] + lb[h][j];
                    float sg = 1.f / (1.f + expf(-z));
                    float slr = 0.6f * z + 0.4f * z * (2.f * sg - 1.f);
                    p += slr * ad[h][j];
                }
                p += __shfl_xor_sync(0xffffffff, p, 1);
                p += __shfl_xor_sync(0xffffffff, p, 2);
                if (q == 0) {
                    int hg = blockIdx.y * 4 + warp_n * 2 + h;
                    out[(size_t)row * 8 + hg] = p;
                }
            }
        }
    }
}

// ===================== launch =====================
extern "C" void kernel_launch(void* const* d_in, const int* in_sizes, int n_in,
                              void* d_out, int out_size) {
    const float* x_edge   = (const float*)d_in[0];
    const float* node_in  = (const float*)d_in[1];
    const float* edge_vec = (const float*)d_in[2];
    const int*   sp       = (const int*)d_in[3];
    const float* dot_w    = (const float*)d_in[4];
    const float* dot_b    = (const float*)d_in[5];
    const float* w0  = (const float*)d_in[6];
    const float* b0  = (const float*)d_in[7];
    const float* w1  = (const float*)d_in[8];
    const float* b1  = (const float*)d_in[9];
    const float* w2  = (const float*)d_in[10];
    const float* b2  = (const float*)d_in[11];
    const float* g0  = (const float*)d_in[12];
    const float* bb0 = (const float*)d_in[13];
    const float* g1  = (const float*)d_in[14];
    const float* bb1 = (const float*)d_in[15];
    const float* fcw = (const float*)d_in[16];
    const float* fcb = (const float*)d_in[17];
    const float* lng = (const float*)d_in[18];
    const float* lnb = (const float*)d_in[19];
    const float* ad  = (const float*)d_in[20];
    float* out = (float*)d_out;

    k1_node<<<NN, 256>>>(node_in, dot_w, dot_b);

    size_t smem2 = (size_t)(EPB * XS_STR + NROWS * CATT + EPB * GN_STR + EPB * 12 +
                            EPB * H_STR + EPB * H_STR + EPB) * sizeof(float);
    cudaFuncSetAttribute(k2_edge, cudaFuncAttributeMaxDynamicSharedMemorySize, (int)smem2);
    dim3 g2(KK / EPB, NN);
    k2_edge<<<g2, 256, smem2>>>(x_edge, edge_vec, sp,
                                w0, b0, w1, b1, w2, b2, g0, bb0, g1, bb1);

    dim3 g3(EE / 128, 2);
    k3_gemm<<<g3, 256>>>(fcw, fcb, lng, lnb, ad, out);
}

// round 4
// speedup vs baseline: 1.5883x; 1.3880x over previous
#include <cuda_runtime.h>
#include <cuda_bf16.h>
#include <math.h>
#include <stdint.h>

#define NN    8192
#define KK    32
#define EE    (NN*KK)      // 262144 edges
#define CIN   128
#define CATT  128
#define NROWS 9
#define RAD3  768

// ---- scratch ----
__device__ float g_node[(size_t)NN * NROWS * CATT];        // 37.7 MB (L2-resident)
__device__ float g_y[(size_t)RAD3 * EE];                   // 805 MB, layout (768, E)

// ===================== K1 ==========
__global__ void k1_node(const float* __restrict__ node_in,
                        const float* __restrict__ dot_w,
                        const float* __restrict__ dot_b) {
    __shared__ __align__(16) float sm[NROWS * CIN];
    int n = blockIdx.x;
    const float* src = node_in + (size_t)n * NROWS * CIN;
    for (int i = threadIdx.x; i < NROWS * CIN; i += blockDim.x) sm[i] = src[i];
    __syncthreads();
    for (int idx = threadIdx.x; idx < NROWS * CATT; idx += blockDim.x) {
        int m = idx >> 7;
        int d = idx & 127;
        int l = (m == 0) ? 0 : (m < 4 ? 1 : 2);
        const float4* w = reinterpret_cast<const float4*>(dot_w + (size_t)l * CATT * CIN + (size_t)d * CIN);
        const float4* x = reinterpret_cast<const float4*>(sm + m * CIN);
        float acc = (m == 0) ? dot_b[d] : 0.f;
#pragma unroll
        for (int c4 = 0; c4 < CIN / 4; c4++) {
            float4 wv = __ldg(&w[c4]);
            float4 xv = x[c4];
            acc += wv.x * xv.x + wv.y * xv.y + wv.z * xv.z + wv.w * xv.w;
        }
        g_node[(size_t)n * NROWS * CATT + idx] = acc;
    }
}

// ===================== shared mma helpers ======================
__device__ __forceinline__ uint32_t sptr(const void* p) {
    return (uint32_t)__cvta_generic_to_shared(p);
}
__device__ __forceinline__ void ldmx4_t(uint32_t addr, uint32_t& r0, uint32_t& r1,
                                        uint32_t& r2, uint32_t& r3) {
    asm volatile("ldmatrix.sync.aligned.m8n8.x4.trans.shared.b16 {%0,%1,%2,%3}, [%4];"
                 : "=r"(r0), "=r"(r1), "=r"(r2), "=r"(r3) : "r"(addr));
}
__device__ __forceinline__ void ldmx4(uint32_t addr, uint32_t& r0, uint32_t& r1,
                                      uint32_t& r2, uint32_t& r3) {
    asm volatile("ldmatrix.sync.aligned.m8n8.x4.shared.b16 {%0,%1,%2,%3}, [%4];"
                 : "=r"(r0), "=r"(r1), "=r"(r2), "=r"(r3) : "r"(addr));
}
__device__ __forceinline__ void mma16816(float* c, const uint32_t* a, const uint32_t* b) {
    asm volatile("mma.sync.aligned.m16n8k16.row.col.f32.bf16.bf16.f32 "
                 "{%0,%1,%2,%3}, {%4,%5,%6,%7}, {%8,%9}, {%0,%1,%2,%3};"
                 : "+f"(c[0]), "+f"(c[1]), "+f"(c[2]), "+f"(c[3])
                 : "r"(a[0]), "r"(a[1]), "r"(a[2]), "r"(a[3]), "r"(b[0]), "r"(b[1]));
}
__device__ __forceinline__ void split_bf16(float v, __nv_bfloat16& hi, __nv_bfloat16& lo) {
    hi = __float2bfloat16(v);
    lo = __float2bfloat16(v - __bfloat162float(hi));
}

// ===================== K2: 64 edges/block, smem weights + tensor-core w2 =====
// smem float offsets
#define OFF_XS    0                      // 64*132 = 8448 (xs, later x0s)
#define OFF_WREG  8448                   // 9216 (w0s 64*132 | W2hi/W2lo bf16)
#define OFF_W1REG (8448+9216)            // 4608 (w1s 64*68 | Hhi/Hlo bf16)
#define OFF_H0    (OFF_W1REG+4608)       // 4352 (64*68)
#define OFF_H1    (OFF_H0+4352)          // 4352
#define OFF_SH    (OFF_H1+4352)          // 768  (64*12)
#define OFF_NF    (OFF_SH+768)           // 2304 (2*1152)
#define OFF_IDX   (OFF_NF+2304)          // 64
#define SMEM2_FLOATS (OFF_IDX+64)        // 34112 floats = 136448 B

__device__ __forceinline__ void ln_silu_par(float* hs, const float* __restrict__ g,
                                            const float* __restrict__ b, int tid) {
    int e = tid >> 2, p = tid & 3;
    float* row = hs + e * 68 + p * 16;
    float v[16];
    float s1 = 0.f, s2 = 0.f;
#pragma unroll
    for (int i = 0; i < 16; i++) { v[i] = row[i]; s1 += v[i]; s2 += v[i] * v[i]; }
    s1 += __shfl_xor_sync(0xffffffff, s1, 1);
    s2 += __shfl_xor_sync(0xffffffff, s2, 1);
    s1 += __shfl_xor_sync(0xffffffff, s1, 2);
    s2 += __shfl_xor_sync(0xffffffff, s2, 2);
    float mean = s1 * (1.f / 64.f);
    float var  = s2 * (1.f / 64.f) - mean * mean;
    float rs   = rsqrtf(var + 1e-5f);
#pragma unroll
    for (int i = 0; i < 16; i++) {
        float z = (v[i] - mean) * rs * __ldg(&g[p * 16 + i]) + __ldg(&b[p * 16 + i]);
        row[i] = z / (1.f + expf(-z));
    }
}

__global__ void __launch_bounds__(256, 1) k2_edge(
    const float* __restrict__ x_edge, const float* __restrict__ edge_vec,
    const int* __restrict__ sp_idx,
    const float* __restrict__ w0, const float* __restrict__ b0,
    const float* __restrict__ w1, const float* __restrict__ b1,
    const float* __restrict__ w2, const float* __restrict__ b2,
    const float* __restrict__ g0, const float* __restrict__ bb0,
    const float* __restrict__ g1, const float* __restrict__ bb1)
{
    extern __shared__ __align__(16) float smem[];
    float* xs    = smem + OFF_XS;
    float* wreg  = smem + OFF_WREG;
    float* w1reg = smem + OFF_W1REG;
    float* h0s   = smem + OFF_H0;
    float* h1s   = smem + OFF_H1;
    float* shs   = smem + OFF_SH;
    float* nfs   = smem + OFF_NF;
    int*   idxs  = (int*)(smem + OFF_IDX);

    __nv_bfloat16* Hhi  = (__nv_bfloat16*)w1reg;          // 64 x 72
    __nv_bfloat16* Hlo  = Hhi + 64 * 72;
    __nv_bfloat16* W2hi = (__nv_bfloat16*)wreg;           // 128 x 72
    __nv_bfloat16* W2lo = W2hi + 128 * 72;

    int tid = threadIdx.x;
    int n0  = blockIdx.x * 2;
    int eg0 = blockIdx.x * 64;          // global edge base

    // ---- stage ----
    if (tid < 64) idxs[tid] = sp_idx[eg0 + tid];
    for (int i = tid; i < 2 * NROWS * CATT; i += 256)
        nfs[i] = g_node[(size_t)n0 * NROWS * CATT + i];
    for (int i = tid; i < 64 * 128; i += 256) {
        int e = i >> 7, c = i & 127;
        xs[e * 132 + c] = x_edge[(size_t)(eg0 + e) * 128 + c];
    }
    for (int i = tid; i < 64 * 128; i += 256) {
        int o = i >> 7, c = i & 127;
        wreg[o * 132 + c] = __ldg(&w0[o * 128 + c]);
    }
    for (int i = tid; i < 64 * 64; i += 256) {
        int o = i >> 6, c = i & 63;
        w1reg[o * 68 + c] = __ldg(&w1[o * 64 + c]);
    }
    if (tid < 64) {
        const float* ev = edge_vec + (size_t)(eg0 + tid) * 3;
        float x = ev[0], y = ev[1], z = ev[2];
        float nrm = sqrtf(x * x + y * y + z * z);
        float inv = 1.f / fmaxf(nrm, 1e-12f);
        x *= inv; y *= inv; z *= inv;
        float* s = shs + tid * 12;
        const float C0 = 0.28209479177387814f;
        const float C1 = 0.4886025119029199f;
        const float C2 = 0.6307831305050401f;
        const float S3 = 1.7320508075688772f;
        s[0] = C0;
        s[1] = C1 * x; s[2] = C1 * y; s[3] = C1 * z;
        s[4] = C2 * S3 * x * z;
        s[5] = C2 * S3 * x * y;
        s[6] = C2 * (y * y - 0.5f * (x * x + z * z));
        s[7] = C2 * S3 * y * z;
        s[8] = C2 * 0.5f * S3 * (z * z - x * x);
    }
    __syncthreads();

    int tx = tid & 15;      // output group
    int ty = tid >> 4;      // edge group
    int o4 = tx * 4, e4 = ty * 4;

    // ---- rad0: 64e x 64o, k=128, SIMT 4x4 tiles ----
    {
        float a[4][4];
        float4 bv = *(const float4*)&b0[o4];
#pragma unroll
        for (int i = 0; i < 4; i++) { a[i][0]=bv.x; a[i][1]=bv.y; a[i][2]=bv.z; a[i][3]=bv.w; }
#pragma unroll 4
        for (int k4 = 0; k4 < 32; k4++) {
            float4 xv[4], wv[4];
#pragma unroll
            for (int i = 0; i < 4; i++) xv[i] = *(const float4*)&xs[(e4 + i) * 132 + k4 * 4];
#pragma unroll
            for (int j = 0; j < 4; j++) wv[j] = *(const float4*)&wreg[(o4 + j) * 132 + k4 * 4];
#pragma unroll
            for (int i = 0; i < 4; i++)
#pragma unroll
                for (int j = 0; j < 4; j++)
                    a[i][j] += xv[i].x * wv[j].x + xv[i].y * wv[j].y +
                               xv[i].z * wv[j].z + xv[i].w * wv[j].w;
        }
#pragma unroll
        for (int i = 0; i < 4; i++)
            *(float4*)&h0s[(e4 + i) * 68 + o4] = make_float4(a[i][0], a[i][1], a[i][2], a[i][3]);
    }
    __syncthreads();
    ln_silu_par(h0s, g0, bb0, tid);
    __syncthreads();

    // ---- rad1: 64e x 64o, k=64 ----
    {
        float a[4][4];
        float4 bv = *(const float4*)&b1[o4];
#pragma unroll
        for (int i = 0; i < 4; i++) { a[i][0]=bv.x; a[i][1]=bv.y; a[i][2]=bv.z; a[i][3]=bv.w; }
#pragma unroll 4
        for (int k4 = 0; k4 < 16; k4++) {
            float4 xv[4], wv[4];
#pragma unroll
            for (int i = 0; i < 4; i++) xv[i] = *(const float4*)&h0s[(e4 + i) * 68 + k4 * 4];
#pragma unroll
            for (int j = 0; j < 4; j++) wv[j] = *(const float4*)&w1reg[(o4 + j) * 68 + k4 * 4];
#pragma unroll
            for (int i = 0; i < 4; i++)
#pragma unroll
                for (int j = 0; j < 4; j++)
                    a[i][j] += xv[i].x * wv[j].x + xv[i].y * wv[j].y +
                               xv[i].z * wv[j].z + xv[i].w * wv[j].w;
        }
#pragma unroll
        for (int i = 0; i < 4; i++)
            *(float4*)&h1s[(e4 + i) * 68 + o4] = make_float4(a[i][0], a[i][1], a[i][2], a[i][3]);
    }
    __syncthreads();
    ln_silu_par(h1s, g1, bb1, tid);
    __syncthreads();

    // ---- h1 -> bf16 hi/lo (overwrites w1s region) ----
    for (int i = tid; i < 64 * 64; i += 256) {
        int e = i >> 6, c = i & 63;
        __nv_bfloat16 hi, lo;
        split_bf16(h1s[e * 68 + c], hi, lo);
        Hhi[e * 72 + c] = hi;
        Hlo[e * 72 + c] = lo;
    }
    __syncthreads();

    // ---- phase B: 6 chunks of 128 j ----
    int lane = tid & 31, warp = tid >> 5;
    int we = warp & 3, wj = warp >> 2;          // e0 = we*16, j0 = wj*64
    int g = lane >> 3, r = lane & 7;
    int h_row = r + ((g & 1) << 3);             // A (row-major H) non-trans
    int h_col = (g >> 1) << 3;
    int b_n   = r + ((g >> 1) << 3);            // B non-trans (as in K3)
    int b_k   = (g & 1) << 3;
    int e_lo = lane >> 2, q = lane & 3;

    for (int b = 0; b < 6; b++) {
        // stage w2 chunk (128 x 64) -> bf16 hi/lo
        for (int i = tid; i < 128 * 64; i += 256) {
            int jr = i >> 6, c = i & 63;
            __nv_bfloat16 hi, lo;
            split_bf16(__ldg(&w2[(size_t)(b * 128 + jr) * 64 + c]), hi, lo);
            W2hi[jr * 72 + c] = hi;
            W2lo[jr * 72 + c] = lo;
        }
        // compute x0 chunk (64 x 128) into xs
        for (int i = tid; i < 64 * 128; i += 256) {
            int e = i >> 7, d = i & 127;
            const float* s = shs + e * 12;
            const float* src;
            if (b & 1) src = g_node + (size_t)idxs[e] * (NROWS * CATT);
            else       src = nfs + (e >> 5) * (NROWS * CATT);
            float x0;
            if      (b < 2) x0 = s[0] * src[d];
            else if (b < 4) x0 = s[1] * src[128 + d] + s[2] * src[256 + d] + s[3] * src[384 + d];
            else            x0 = s[4] * src[512 + d] + s[5] * src[640 + d] + s[6] * src[768 + d]
                               + s[7] * src[896 + d] + s[8] * src[1024 + d];
            xs[e * 132 + d] = x0;
        }
        __syncthreads();

        // mma: edge_m0 chunk [64e x 128j] = H(64x64) @ W2chunk^T
        float acc2[4][2][4];
#pragma unroll
        for (int np = 0; np < 4; np++)
#pragma unroll
            for (int n8 = 0; n8 < 2; n8++)
#pragma unroll
                for (int c = 0; c < 4; c++) acc2[np][n8][c] = 0.f;

#pragma unroll
        for (int kk = 0; kk < 4; kk++) {
            uint32_t ah[4], al[4];
            uint32_t aad = sptr(&Hhi[(we * 16 + h_row) * 72 + kk * 16 + h_col]);
            uint32_t aal = sptr(&Hlo[(we * 16 + h_row) * 72 + kk * 16 + h_col]);
            ldmx4(aad, ah[0], ah[1], ah[2], ah[3]);
            ldmx4(aal, al[0], al[1], al[2], al[3]);
#pragma unroll
            for (int np = 0; np < 4; np++) {
                uint32_t bh[4], bl[4];
                uint32_t bad = sptr(&W2hi[(wj * 64 + np * 16 + b_n) * 72 + kk * 16 + b_k]);
                uint32_t bal = sptr(&W2lo[(wj * 64 + np * 16 + b_n) * 72 + kk * 16 + b_k]);
                ldmx4(bad, bh[0], bh[1], bh[2], bh[3]);
                ldmx4(bal, bl[0], bl[1], bl[2], bl[3]);
#pragma unroll
                for (int n8 = 0; n8 < 2; n8++) {
                    float* c = acc2[np][n8];
                    mma16816(c, ah, &bh[n8 * 2]);
                    mma16816(c, al, &bh[n8 * 2]);
                    mma16816(c, ah, &bl[n8 * 2]);
                }
            }
        }

        // y = x0 * (edge_m0 + b2), write to g_y
#pragma unroll
        for (int np = 0; np < 4; np++) {
#pragma unroll
            for (int n8 = 0; n8 < 2; n8++) {
                int jl = wj * 64 + np * 16 + n8 * 8 + 2 * q;
                int jgl = b * 128 + jl;
                float b2v0 = __ldg(&b2[jgl]);
                float b2v1 = __ldg(&b2[jgl + 1]);
#pragma unroll
                for (int half = 0; half < 2; half++) {
                    int e = we * 16 + e_lo + half * 8;
                    float y0 = xs[e * 132 + jl]     * (acc2[np][n8][half * 2]     + b2v0);
                    float y1 = xs[e * 132 + jl + 1] * (acc2[np][n8][half * 2 + 1] + b2v1);
                    g_y[(size_t)jgl * EE + eg0 + e]       = y0;
                    g_y[(size_t)(jgl + 1) * EE + eg0 + e] = y1;
                }
            }
        }
        __syncthreads();
    }
}

// ===================== K3 (unchanged, verified) ======
#define A_STR 136
#define B_STR 40

__global__ void __launch_bounds__(256) k3_gemm(
    const float* __restrict__ fc_w, const float* __restrict__ fc_b,
    const float* __restrict__ ln_g, const float* __restrict__ ln_b,
    const float* __restrict__ alpha_dot, float* __restrict__ out)
{
    __shared__ __align__(16) __nv_bfloat16 Ahi[32 * A_STR];
    __shared__ __align__(16) __nv_bfloat16 Alo[32 * A_STR];
    __shared__ __align__(16) __nv_bfloat16 Bhi[128 * B_STR];
    __shared__ __align__(16) __nv_bfloat16 Blo[128 * B_STR];

    int tid  = threadIdx.x;
    int lane = tid & 31;
    int warp = tid >> 5;
    int warp_m = warp >> 1;
    int warp_n = warp & 1;
    int m0  = blockIdx.x * 128;
    int n0g = blockIdx.y * 128;

    float acc[2][8][4];
#pragma unroll
    for (int i = 0; i < 2; i++)
#pragma unroll
        for (int f = 0; f < 8; f++)
#pragma unroll
            for (int j = 0; j < 4; j++) acc[i][f][j] = 0.f;

    int g = lane >> 3, r = lane & 7;
    int a_k  = r + ((g >> 1) << 3);
    int a_e  = ((g & 1) << 3);
    int b_n  = r + ((g >> 1) << 3);
    int b_k  = ((g & 1) << 3);

    for (int k0 = 0; k0 < 768; k0 += 32) {
#pragma unroll
        for (int p = 0; p < 4; p++) {
            int krow = (tid >> 5) + p * 8;
            int e4   = (tid & 31) * 4;
            float4 v = *reinterpret_cast<const float4*>(&g_y[(size_t)(k0 + krow) * EE + m0 + e4]);
            __nv_bfloat16 h0,h1,h2,h3,l0,l1,l2,l3;
            split_bf16(v.x, h0, l0); split_bf16(v.y, h1, l1);
            split_bf16(v.z, h2, l2); split_bf16(v.w, h3, l3);
            __nv_bfloat162* dh = reinterpret_cast<__nv_bfloat162*>(&Ahi[krow * A_STR + e4]);
            __nv_bfloat162* dl = reinterpret_cast<__nv_bfloat162*>(&Alo[krow * A_STR + e4]);
            dh[0] = __nv_bfloat162(h0, h1); dh[1] = __nv_bfloat162(h2, h3);
            dl[0] = __nv_bfloat162(l0, l1); dl[1] = __nv_bfloat162(l2, l3);
        }
#pragma unroll
        for (int p = 0; p < 4; p++) {
            int nrow = (tid >> 3) + p * 32;
            int k4   = (tid & 7) * 4;
            float4 v = __ldg(reinterpret_cast<const float4*>(&fc_w[(size_t)(n0g + nrow) * 768 + k0 + k4]));
            __nv_bfloat16 h0,h1,h2,h3,l0,l1,l2,l3;
            split_bf16(v.x, h0, l0); split_bf16(v.y, h1, l1);
            split_bf16(v.z, h2, l2); split_bf16(v.w, h3, l3);
            __nv_bfloat162* dh = reinterpret_cast<__nv_bfloat162*>(&Bhi[nrow * B_STR + k4]);
            __nv_bfloat162* dl = reinterpret_cast<__nv_bfloat162*>(&Blo[nrow * B_STR + k4]);
            dh[0] = __nv_bfloat162(h0, h1); dh[1] = __nv_bfloat162(h2, h3);
            dl[0] = __nv_bfloat162(l0, l1); dl[1] = __nv_bfloat162(l2, l3);
        }
        __syncthreads();

#pragma unroll
        for (int kh = 0; kh < 2; kh++) {
            uint32_t ah[2][4], al[2][4];
#pragma unroll
            for (int mf = 0; mf < 2; mf++) {
                int e0 = warp_m * 32 + mf * 16;
                uint32_t ad_hi = sptr(&Ahi[(kh * 16 + a_k) * A_STR + e0 + a_e]);
                uint32_t ad_lo = sptr(&Alo[(kh * 16 + a_k) * A_STR + e0 + a_e]);
                ldmx4_t(ad_hi, ah[mf][0], ah[mf][1], ah[mf][2], ah[mf][3]);
                ldmx4_t(ad_lo, al[mf][0], al[mf][1], al[mf][2], al[mf][3]);
            }
#pragma unroll
            for (int np = 0; np < 4; np++) {
                int nb = warp_n * 64 + np * 16;
                uint32_t bh[4], bl[4];
                uint32_t bd_hi = sptr(&Bhi[(nb + b_n) * B_STR + kh * 16 + b_k]);
                uint32_t bd_lo = sptr(&Blo[(nb + b_n) * B_STR + kh * 16 + b_k]);
                ldmx4(bd_hi, bh[0], bh[1], bh[2], bh[3]);
                ldmx4(bd_lo, bl[0], bl[1], bl[2], bl[3]);
#pragma unroll
                for (int mf = 0; mf < 2; mf++) {
#pragma unroll
                    for (int half8 = 0; half8 < 2; half8++) {
                        float* c = acc[mf][2 * np + half8];
                        mma16816(c, ah[mf], &bh[half8 * 2]);
                        mma16816(c, al[mf], &bh[half8 * 2]);
                        mma16816(c, ah[mf], &bl[half8 * 2]);
                    }
                }
            }
        }
        __syncthreads();
    }

    int q = lane & 3;
    float lg[2][8], lb[2][8], ad[2][8], bias[2][8];
#pragma unroll
    for (int h = 0; h < 2; h++) {
        int hg = blockIdx.y * 4 + warp_n * 2 + h;
#pragma unroll
        for (int fq = 0; fq < 4; fq++) {
#pragma unroll
            for (int j = 0; j < 2; j++) {
                int d   = fq * 8 + q * 2 + j;
                int col = n0g + warp_n * 64 + h * 32 + d;
                lg[h][fq * 2 + j]   = __ldg(&ln_g[d]);
                lb[h][fq * 2 + j]   = __ldg(&ln_b[d]);
                ad[h][fq * 2 + j]   = __ldg(&alpha_dot[hg * 32 + d]);
                bias[h][fq * 2 + j] = __ldg(&fc_b[col]);
            }
        }
    }

#pragma unroll
    for (int mf = 0; mf < 2; mf++) {
#pragma unroll
        for (int half8 = 0; half8 < 2; half8++) {
            int row = m0 + warp_m * 32 + mf * 16 + (lane >> 2) + half8 * 8;
#pragma unroll
            for (int h = 0; h < 2; h++) {
                float v[8];
#pragma unroll
                for (int fq = 0; fq < 4; fq++) {
                    int f = 4 * h + fq;
                    v[fq * 2 + 0] = acc[mf][f][half8 * 2 + 0] + bias[h][fq * 2 + 0];
                    v[fq * 2 + 1] = acc[mf][f][half8 * 2 + 1] + bias[h][fq * 2 + 1];
                }
                float s1 = 0.f, s2 = 0.f;
#pragma unroll
                for (int j = 0; j < 8; j++) { s1 += v[j]; s2 += v[j] * v[j]; }
                s1 += __shfl_xor_sync(0xffffffff, s1, 1);
                s2 += __shfl_xor_sync(0xffffffff, s2, 1);
                s1 += __shfl_xor_sync(0xffffffff, s1, 2);
                s2 += __shfl_xor_sync(0xffffffff, s2, 2);
                float mean = s1 * (1.f / 32.f);
                float var  = s2 * (1.f / 32.f) - mean * mean;
                float rs   = rsqrtf(var + 1e-5f);
                float p = 0.f;
#pragma unroll
                for (int j = 0; j < 8; j++) {
                    float z = (v[j] - mean) * rs * lg[h][j] + lb[h][j];
                    float sg = 1.f / (1.f + expf(-z));
                    float slr = 0.6f * z + 0.4f * z * (2.f * sg - 1.f);
                    p += slr * ad[h][j];
                }
                p += __shfl_xor_sync(0xffffffff, p, 1);
                p += __shfl_xor_sync(0xffffffff, p, 2);
                if (q == 0) {
                    int hg = blockIdx.y * 4 + warp_n * 2 + h;
                    out[(size_t)row * 8 + hg] = p;
                }
            }
        }
    }
}

// ===================== launch =====================
extern "C" void kernel_launch(void* const* d_in, const int* in_sizes, int n_in,
                              void* d_out, int out_size) {
    const float* x_edge   = (const float*)d_in[0];
    const float* node_in  = (const float*)d_in[1];
    const float* edge_vec = (const float*)d_in[2];
    const int*   sp       = (const int*)d_in[3];
    const float* dot_w    = (const float*)d_in[4];
    const float* dot_b    = (const float*)d_in[5];
    const float* w0  = (const float*)d_in[6];
    const float* b0  = (const float*)d_in[7];
    const float* w1  = (const float*)d_in[8];
    const float* b1  = (const float*)d_in[9];
    const float* w2  = (const float*)d_in[10];
    const float* b2  = (const float*)d_in[11];
    const float* g0  = (const float*)d_in[12];
    const float* bb0 = (const float*)d_in[13];
    const float* g1  = (const float*)d_in[14];
    const float* bb1 = (const float*)d_in[15];
    const float* fcw = (const float*)d_in[16];
    const float* fcb = (const float*)d_in[17];
    const float* lng = (const float*)d_in[18];
    const float* lnb = (const float*)d_in[19];
    const float* ad  = (const float*)d_in[20];
    float* out = (float*)d_out;

    k1_node<<<NN, 256>>>(node_in, dot_w, dot_b);

    size_t smem2 = (size_t)SMEM2_FLOATS * sizeof(float);
    cudaFuncSetAttribute(k2_edge, cudaFuncAttributeMaxDynamicSharedMemorySize, (int)smem2);
    k2_edge<<<NN / 2, 256, smem2>>>(x_edge, edge_vec, sp,
                                    w0, b0, w1, b1, w2, b2, g0, bb0, g1, bb1);

    dim3 g3(EE / 128, 2);
    k3_gemm<<<g3, 256>>>(fcw, fcb, lng, lnb, ad, out);
}

// round 5
// speedup vs baseline: 1.8447x; 1.1614x over previous
#include <cuda_runtime.h>
#include <cuda_bf16.h>
#include <math.h>
#include <stdint.h>

#define NN    8192
#define KK    32
#define EE    (NN*KK)      // 262144 edges
#define CIN   128
#define CATT  128
#define NROWS 9
#define RAD3  768

// ---- scratch ----
__device__ float g_node[(size_t)NN * NROWS * CATT];        // 37.7 MB (L2-resident)

// ===================== K1 ==========
__global__ void k1_node(const float* __restrict__ node_in,
                        const float* __restrict__ dot_w,
                        const float* __restrict__ dot_b) {
    __shared__ __align__(16) float sm[NROWS * CIN];
    int n = blockIdx.x;
    const float* src = node_in + (size_t)n * NROWS * CIN;
    for (int i = threadIdx.x; i < NROWS * CIN; i += blockDim.x) sm[i] = src[i];
    __syncthreads();
    for (int idx = threadIdx.x; idx < NROWS * CATT; idx += blockDim.x) {
        int m = idx >> 7;
        int d = idx & 127;
        int l = (m == 0) ? 0 : (m < 4 ? 1 : 2);
        const float4* w = reinterpret_cast<const float4*>(dot_w + (size_t)l * CATT * CIN + (size_t)d * CIN);
        const float4* x = reinterpret_cast<const float4*>(sm + m * CIN);
        float acc = (m == 0) ? dot_b[d] : 0.f;
#pragma unroll
        for (int c4 = 0; c4 < CIN / 4; c4++) {
            float4 wv = __ldg(&w[c4]);
            float4 xv = x[c4];
            acc += wv.x * xv.x + wv.y * xv.y + wv.z * xv.z + wv.w * xv.w;
        }
        g_node[(size_t)n * NROWS * CATT + idx] = acc;
    }
}

// ===================== mma helpers ======================
__device__ __forceinline__ uint32_t sptr(const void* p) {
    return (uint32_t)__cvta_generic_to_shared(p);
}
__device__ __forceinline__ void ldmx4(uint32_t addr, uint32_t& r0, uint32_t& r1,
                                      uint32_t& r2, uint32_t& r3) {
    asm volatile("ldmatrix.sync.aligned.m8n8.x4.shared.b16 {%0,%1,%2,%3}, [%4];"
                 : "=r"(r0), "=r"(r1), "=r"(r2), "=r"(r3) : "r"(addr));
}
__device__ __forceinline__ void mma16816(float* c, const uint32_t* a, const uint32_t* b) {
    asm volatile("mma.sync.aligned.m16n8k16.row.col.f32.bf16.bf16.f32 "
                 "{%0,%1,%2,%3}, {%4,%5,%6,%7}, {%8,%9}, {%0,%1,%2,%3};"
                 : "+f"(c[0]), "+f"(c[1]), "+f"(c[2]), "+f"(c[3])
                 : "r"(a[0]), "r"(a[1]), "r"(a[2]), "r"(a[3]), "r"(b[0]), "r"(b[1]));
}
__device__ __forceinline__ void split_bf16(float v, __nv_bfloat16& hi, __nv_bfloat16& lo) {
    hi = __float2bfloat16(v);
    lo = __float2bfloat16(v - __bfloat162float(hi));
}

// ===================== K2 fused: MLP + w2-mma + FC GEMM + epilogue ===========
// smem float offsets
#define OFF_XS    0                        // 8448: x_edge staging, then x0 chunks
#define OFF_WREG  8448                     // 9216: w0s(64x132) | W2hi/W2lo (128x72 bf16 each)
#define OFF_W1REG (8448+9216)              // 4608: w1s(64x68)  | Hhi/Hlo (64x72 bf16 each)
#define OFF_H0    (OFF_W1REG+4608)         // 4352: h0s | Yhi (64x136 bf16)
#define OFF_H1    (OFF_H0+4352)            // 4352: h1s | Ylo (64x136 bf16)
#define OFF_SH    (OFF_H1+4352)            // 768
#define OFF_NF    (OFF_SH+768)             // 2304
#define OFF_IDX   (OFF_NF+2304)            // 64
#define OFF_FCW   (OFF_IDX+64)             // 17408: FCWhi/FCWlo (128x136 bf16 each)
#define SMEM2_FLOATS (OFF_FCW+17408)       // 51520 floats = 206080 B

__device__ __forceinline__ void ln_silu_par(float* hs, const float* __restrict__ g,
                                            const float* __restrict__ b, int tid) {
    int e = tid >> 2, p = tid & 3;
    float* row = hs + e * 68 + p * 16;
    float v[16];
    float s1 = 0.f, s2 = 0.f;
#pragma unroll
    for (int i = 0; i < 16; i++) { v[i] = row[i]; s1 += v[i]; s2 += v[i] * v[i]; }
    s1 += __shfl_xor_sync(0xffffffff, s1, 1);
    s2 += __shfl_xor_sync(0xffffffff, s2, 1);
    s1 += __shfl_xor_sync(0xffffffff, s1, 2);
    s2 += __shfl_xor_sync(0xffffffff, s2, 2);
    float mean = s1 * (1.f / 64.f);
    float var  = s2 * (1.f / 64.f) - mean * mean;
    float rs   = rsqrtf(var + 1e-5f);
#pragma unroll
    for (int i = 0; i < 16; i++) {
        float z = (v[i] - mean) * rs * __ldg(&g[p * 16 + i]) + __ldg(&b[p * 16 + i]);
        row[i] = z / (1.f + expf(-z));
    }
}

__global__ void __launch_bounds__(256, 1) k2_fused(
    const float* __restrict__ x_edge, const float* __restrict__ edge_vec,
    const int* __restrict__ sp_idx,
    const float* __restrict__ w0, const float* __restrict__ b0,
    const float* __restrict__ w1, const float* __restrict__ b1,
    const float* __restrict__ w2, const float* __restrict__ b2,
    const float* __restrict__ g0, const float* __restrict__ bb0,
    const float* __restrict__ g1, const float* __restrict__ bb1,
    const float* __restrict__ fc_w, const float* __restrict__ fc_b,
    const float* __restrict__ ln_g, const float* __restrict__ ln_b,
    const float* __restrict__ alpha_dot, float* __restrict__ out)
{
    extern __shared__ __align__(16) float smem[];
    float* xs    = smem + OFF_XS;
    float* wreg  = smem + OFF_WREG;
    float* w1reg = smem + OFF_W1REG;
    float* h0s   = smem + OFF_H0;
    float* h1s   = smem + OFF_H1;
    float* shs   = smem + OFF_SH;
    float* nfs   = smem + OFF_NF;
    int*   idxs  = (int*)(smem + OFF_IDX);

    __nv_bfloat16* Hhi   = (__nv_bfloat16*)w1reg;         // 64 x 72
    __nv_bfloat16* Hlo   = Hhi + 64 * 72;
    __nv_bfloat16* W2hi  = (__nv_bfloat16*)wreg;          // 128 x 72
    __nv_bfloat16* W2lo  = W2hi + 128 * 72;
    __nv_bfloat16* Yhi   = (__nv_bfloat16*)h0s;           // 64 x 136
    __nv_bfloat16* Ylo   = (__nv_bfloat16*)h1s;           // 64 x 136
    __nv_bfloat16* FCWhi = (__nv_bfloat16*)(smem + OFF_FCW);  // 128 x 136
    __nv_bfloat16* FCWlo = FCWhi + 128 * 136;

    int tid = threadIdx.x;
    int n0  = blockIdx.x * 2;
    int eg0 = blockIdx.x * 64;          // global edge base

    // ---- stage ----
    if (tid < 64) idxs[tid] = sp_idx[eg0 + tid];
    for (int i = tid; i < 2 * NROWS * CATT; i += 256)
        nfs[i] = g_node[(size_t)n0 * NROWS * CATT + i];
    for (int i = tid; i < 64 * 128; i += 256) {
        int e = i >> 7, c = i & 127;
        xs[e * 132 + c] = x_edge[(size_t)(eg0 + e) * 128 + c];
    }
    for (int i = tid; i < 64 * 128; i += 256) {
        int o = i >> 7, c = i & 127;
        wreg[o * 132 + c] = __ldg(&w0[o * 128 + c]);
    }
    for (int i = tid; i < 64 * 64; i += 256) {
        int o = i >> 6, c = i & 63;
        w1reg[o * 68 + c] = __ldg(&w1[o * 64 + c]);
    }
    if (tid < 64) {
        const float* ev = edge_vec + (size_t)(eg0 + tid) * 3;
        float x = ev[0], y = ev[1], z = ev[2];
        float nrm = sqrtf(x * x + y * y + z * z);
        float inv = 1.f / fmaxf(nrm, 1e-12f);
        x *= inv; y *= inv; z *= inv;
        float* s = shs + tid * 12;
        const float C0 = 0.28209479177387814f;
        const float C1 = 0.4886025119029199f;
        const float C2 = 0.6307831305050401f;
        const float S3 = 1.7320508075688772f;
        s[0] = C0;
        s[1] = C1 * x; s[2] = C1 * y; s[3] = C1 * z;
        s[4] = C2 * S3 * x * z;
        s[5] = C2 * S3 * x * y;
        s[6] = C2 * (y * y - 0.5f * (x * x + z * z));
        s[7] = C2 * S3 * y * z;
        s[8] = C2 * 0.5f * S3 * (z * z - x * x);
    }
    __syncthreads();

    int tx = tid & 15;      // output group
    int ty = tid >> 4;      // edge group
    int o4 = tx * 4, e4 = ty * 4;

    // ---- rad0: 64e x 64o, k=128 ----
    {
        float a[4][4];
        float4 bv = *(const float4*)&b0[o4];
#pragma unroll
        for (int i = 0; i < 4; i++) { a[i][0]=bv.x; a[i][1]=bv.y; a[i][2]=bv.z; a[i][3]=bv.w; }
#pragma unroll 4
        for (int k4 = 0; k4 < 32; k4++) {
            float4 xv[4], wv[4];
#pragma unroll
            for (int i = 0; i < 4; i++) xv[i] = *(const float4*)&xs[(e4 + i) * 132 + k4 * 4];
#pragma unroll
            for (int j = 0; j < 4; j++) wv[j] = *(const float4*)&wreg[(o4 + j) * 132 + k4 * 4];
#pragma unroll
            for (int i = 0; i < 4; i++)
#pragma unroll
                for (int j = 0; j < 4; j++)
                    a[i][j] += xv[i].x * wv[j].x + xv[i].y * wv[j].y +
                               xv[i].z * wv[j].z + xv[i].w * wv[j].w;
        }
#pragma unroll
        for (int i = 0; i < 4; i++)
            *(float4*)&h0s[(e4 + i) * 68 + o4] = make_float4(a[i][0], a[i][1], a[i][2], a[i][3]);
    }
    __syncthreads();
    ln_silu_par(h0s, g0, bb0, tid);
    __syncthreads();

    // ---- rad1: 64e x 64o, k=64 ----
    {
        float a[4][4];
        float4 bv = *(const float4*)&b1[o4];
#pragma unroll
        for (int i = 0; i < 4; i++) { a[i][0]=bv.x; a[i][1]=bv.y; a[i][2]=bv.z; a[i][3]=bv.w; }
#pragma unroll 4
        for (int k4 = 0; k4 < 16; k4++) {
            float4 xv[4], wv[4];
#pragma unroll
            for (int i = 0; i < 4; i++) xv[i] = *(const float4*)&h0s[(e4 + i) * 68 + k4 * 4];
#pragma unroll
            for (int j = 0; j < 4; j++) wv[j] = *(const float4*)&w1reg[(o4 + j) * 68 + k4 * 4];
#pragma unroll
            for (int i = 0; i < 4; i++)
#pragma unroll
                for (int j = 0; j < 4; j++)
                    a[i][j] += xv[i].x * wv[j].x + xv[i].y * wv[j].y +
                               xv[i].z * wv[j].z + xv[i].w * wv[j].w;
        }
#pragma unroll
        for (int i = 0; i < 4; i++)
            *(float4*)&h1s[(e4 + i) * 68 + o4] = make_float4(a[i][0], a[i][1], a[i][2], a[i][3]);
    }
    __syncthreads();
    ln_silu_par(h1s, g1, bb1, tid);
    __syncthreads();

    // ---- h1 -> bf16 hi/lo into Hhi/Hlo (overwrites w1s; h1s still source) ----
    {
        float hv[16];
        int e = tid >> 2, p = tid & 3;
#pragma unroll
        for (int i = 0; i < 16; i++) hv[i] = h1s[e * 68 + p * 16 + i];
        __syncthreads();   // all reads of h1s done before Hhi/Hlo (aliases w1s) write? (different region; sync guards h1s later reuse as Ylo)
#pragma unroll
        for (int i = 0; i < 16; i++) {
            __nv_bfloat16 hi, lo;
            split_bf16(hv[i], hi, lo);
            Hhi[e * 72 + p * 16 + i] = hi;
            Hlo[e * 72 + p * 16 + i] = lo;
        }
    }
    __syncthreads();

    // ---- warp roles ----
    int lane = tid & 31, warp = tid >> 5;
    int we   = warp & 3, wj = warp >> 2;        // w2-mma: e0=we*16, j0=wj*64
    int wsub = warp & 1, we2 = warp >> 1;       // FC-mma: e0=we2*16, nsub0=wsub*64
    int g = lane >> 3, r = lane & 7;
    int h_row = r + ((g & 1) << 3);             // A non-trans (row-major)
    int h_col = (g >> 1) << 3;
    int b_n   = r + ((g >> 1) << 3);            // B non-trans
    int b_k   = (g & 1) << 3;
    int e_lo = lane >> 2, q = lane & 3;

    float acc[2][8][4];                         // FC accum: [n-half][n8-tile][frag]
#pragma unroll
    for (int a0 = 0; a0 < 2; a0++)
#pragma unroll
        for (int a1 = 0; a1 < 8; a1++)
#pragma unroll
            for (int a2 = 0; a2 < 4; a2++) acc[a0][a1][a2] = 0.f;

    // ---- 6 chunks of 128 k ----
    for (int b = 0; b < 6; b++) {
        __syncthreads();
        // stage w2 chunk (128 x 64) -> W2hi/W2lo
        for (int i = tid; i < 128 * 16; i += 256) {
            int jr = i >> 4, c4 = (i & 15) * 4;
            float4 v = __ldg(reinterpret_cast<const float4*>(&w2[(size_t)(b * 128 + jr) * 64 + c4]));
            __nv_bfloat16 h0b,h1b,h2b,h3b,l0b,l1b,l2b,l3b;
            split_bf16(v.x, h0b, l0b); split_bf16(v.y, h1b, l1b);
            split_bf16(v.z, h2b, l2b); split_bf16(v.w, h3b, l3b);
            __nv_bfloat162* dh = reinterpret_cast<__nv_bfloat162*>(&W2hi[jr * 72 + c4]);
            __nv_bfloat162* dl = reinterpret_cast<__nv_bfloat162*>(&W2lo[jr * 72 + c4]);
            dh[0] = __nv_bfloat162(h0b, h1b); dh[1] = __nv_bfloat162(h2b, h3b);
            dl[0] = __nv_bfloat162(l0b, l1b); dl[1] = __nv_bfloat162(l2b, l3b);
        }
        // compute x0 chunk (64 x 128) into xs
        for (int i = tid; i < 64 * 128; i += 256) {
            int e = i >> 7, d = i & 127;
            const float* s = shs + e * 12;
            const float* src;
            if (b & 1) src = g_node + (size_t)idxs[e] * (NROWS * CATT);
            else       src = nfs + (e >> 5) * (NROWS * CATT);
            float x0;
            if      (b < 2) x0 = s[0] * src[d];
            else if (b < 4) x0 = s[1] * src[128 + d] + s[2] * src[256 + d] + s[3] * src[384 + d];
            else            x0 = s[4] * src[512 + d] + s[5] * src[640 + d] + s[6] * src[768 + d]
                               + s[7] * src[896 + d] + s[8] * src[1024 + d];
            xs[e * 132 + d] = x0;
        }
        __syncthreads();

        // w2-mma: edge_m0 chunk [64e x 128j] = H(64x64) @ W2chunk^T; y -> Yhi/Ylo
        {
            float acc2[4][2][4];
#pragma unroll
            for (int np = 0; np < 4; np++)
#pragma unroll
                for (int n8 = 0; n8 < 2; n8++)
#pragma unroll
                    for (int c = 0; c < 4; c++) acc2[np][n8][c] = 0.f;

#pragma unroll
            for (int kk = 0; kk < 4; kk++) {
                uint32_t ah[4], al[4];
                ldmx4(sptr(&Hhi[(we * 16 + h_row) * 72 + kk * 16 + h_col]), ah[0], ah[1], ah[2], ah[3]);
                ldmx4(sptr(&Hlo[(we * 16 + h_row) * 72 + kk * 16 + h_col]), al[0], al[1], al[2], al[3]);
#pragma unroll
                for (int np = 0; np < 4; np++) {
                    uint32_t bh[4], bl[4];
                    ldmx4(sptr(&W2hi[(wj * 64 + np * 16 + b_n) * 72 + kk * 16 + b_k]), bh[0], bh[1], bh[2], bh[3]);
                    ldmx4(sptr(&W2lo[(wj * 64 + np * 16 + b_n) * 72 + kk * 16 + b_k]), bl[0], bl[1], bl[2], bl[3]);
#pragma unroll
                    for (int n8 = 0; n8 < 2; n8++) {
                        float* c = acc2[np][n8];
                        mma16816(c, ah, &bh[n8 * 2]);
                        mma16816(c, al, &bh[n8 * 2]);
                        mma16816(c, ah, &bl[n8 * 2]);
                    }
                }
            }

            // y = x0 * (edge_m0 + b2) -> split bf16 -> Yhi/Ylo smem
#pragma unroll
            for (int np = 0; np < 4; np++) {
#pragma unroll
                for (int n8 = 0; n8 < 2; n8++) {
                    int jl = wj * 64 + np * 16 + n8 * 8 + 2 * q;
                    int jgl = b * 128 + jl;
                    float b2v0 = __ldg(&b2[jgl]);
                    float b2v1 = __ldg(&b2[jgl + 1]);
#pragma unroll
                    for (int half = 0; half < 2; half++) {
                        int e = we * 16 + e_lo + half * 8;
                        float2 x0v = *(const float2*)&xs[e * 132 + jl];
                        float y0 = x0v.x * (acc2[np][n8][half * 2]     + b2v0);
                        float y1 = x0v.y * (acc2[np][n8][half * 2 + 1] + b2v1);
                        __nv_bfloat16 yh0, yl0, yh1, yl1;
                        split_bf16(y0, yh0, yl0);
                        split_bf16(y1, yh1, yl1);
                        *reinterpret_cast<__nv_bfloat162*>(&Yhi[e * 136 + jl]) = __nv_bfloat162(yh0, yh1);
                        *reinterpret_cast<__nv_bfloat162*>(&Ylo[e * 136 + jl]) = __nv_bfloat162(yl0, yl1);
                    }
                }
            }
        }

        // FC accumulate over the two n-halves
#pragma unroll
        for (int hf = 0; hf < 2; hf++) {
            __syncthreads();
            // stage fc_w half (128n x 128k) -> FCWhi/FCWlo
            for (int i = tid; i < 128 * 32; i += 256) {
                int nr = i >> 5, k4 = (i & 31) * 4;
                float4 v = __ldg(reinterpret_cast<const float4*>(
                    &fc_w[(size_t)(hf * 128 + nr) * RAD3 + b * 128 + k4]));
                __nv_bfloat16 h0b,h1b,h2b,h3b,l0b,l1b,l2b,l3b;
                split_bf16(v.x, h0b, l0b); split_bf16(v.y, h1b, l1b);
                split_bf16(v.z, h2b, l2b); split_bf16(v.w, h3b, l3b);
                __nv_bfloat162* dh = reinterpret_cast<__nv_bfloat162*>(&FCWhi[nr * 136 + k4]);
                __nv_bfloat162* dl = reinterpret_cast<__nv_bfloat162*>(&FCWlo[nr * 136 + k4]);
                dh[0] = __nv_bfloat162(h0b, h1b); dh[1] = __nv_bfloat162(h2b, h3b);
                dl[0] = __nv_bfloat162(l0b, l1b); dl[1] = __nv_bfloat162(l2b, l3b);
            }
            __syncthreads();
#pragma unroll
            for (int kk = 0; kk < 8; kk++) {
                uint32_t ah[4], al[4];
                ldmx4(sptr(&Yhi[(we2 * 16 + h_row) * 136 + kk * 16 + h_col]), ah[0], ah[1], ah[2], ah[3]);
                ldmx4(sptr(&Ylo[(we2 * 16 + h_row) * 136 + kk * 16 + h_col]), al[0], al[1], al[2], al[3]);
#pragma unroll
                for (int np = 0; np < 4; np++) {
                    uint32_t bh[4], bl[4];
                    ldmx4(sptr(&FCWhi[(wsub * 64 + np * 16 + b_n) * 136 + kk * 16 + b_k]), bh[0], bh[1], bh[2], bh[3]);
                    ldmx4(sptr(&FCWlo[(wsub * 64 + np * 16 + b_n) * 136 + kk * 16 + b_k]), bl[0], bl[1], bl[2], bl[3]);
#pragma unroll
                    for (int n8 = 0; n8 < 2; n8++) {
                        float* c = acc[hf][np * 2 + n8];
                        mma16816(c, ah, &bh[n8 * 2]);
                        mma16816(c, al, &bh[n8 * 2]);
                        mma16816(c, ah, &bl[n8 * 2]);
                    }
                }
            }
        }
    }

    // ---- epilogue: bias, per-head LN(32), smooth-leaky, alpha dot ----
#pragma unroll
    for (int hf = 0; hf < 2; hf++) {
#pragma unroll
        for (int half8 = 0; half8 < 2; half8++) {
            int erow = eg0 + we2 * 16 + e_lo + half8 * 8;
#pragma unroll
            for (int hd = 0; hd < 2; hd++) {
                int hg = hf * 4 + wsub * 2 + hd;
                float v[8];
#pragma unroll
                for (int tt = 0; tt < 4; tt++) {
#pragma unroll
                    for (int c = 0; c < 2; c++) {
                        int d  = tt * 8 + 2 * q + c;
                        int ng = hf * 128 + wsub * 64 + hd * 32 + d;
                        v[tt * 2 + c] = acc[hf][hd * 4 + tt][half8 * 2 + c] + __ldg(&fc_b[ng]);
                    }
                }
                float s1 = 0.f, s2 = 0.f;
#pragma unroll
                for (int j = 0; j < 8; j++) { s1 += v[j]; s2 += v[j] * v[j]; }
                s1 += __shfl_xor_sync(0xffffffff, s1, 1);
                s2 += __shfl_xor_sync(0xffffffff, s2, 1);
                s1 += __shfl_xor_sync(0xffffffff, s1, 2);
                s2 += __shfl_xor_sync(0xffffffff, s2, 2);
                float mean = s1 * (1.f / 32.f);
                float var  = s2 * (1.f / 32.f) - mean * mean;
                float rs   = rsqrtf(var + 1e-5f);
                float p = 0.f;
#pragma unroll
                for (int j = 0; j < 8; j++) {
                    int d = (j >> 1) * 8 + 2 * q + (j & 1);
                    float z = (v[j] - mean) * rs * __ldg(&ln_g[d]) + __ldg(&ln_b[d]);
                    float sg = 1.f / (1.f + expf(-z));
                    float slr = 0.6f * z + 0.4f * z * (2.f * sg - 1.f);
                    p += slr * __ldg(&alpha_dot[hg * 32 + d]);
                }
                p += __shfl_xor_sync(0xffffffff, p, 1);
                p += __shfl_xor_sync(0xffffffff, p, 2);
                if (q == 0)
                    out[(size_t)erow * 8 + hg] = p;
            }
        }
    }
}

// ===================== launch =====================
extern "C" void kernel_launch(void* const* d_in, const int* in_sizes, int n_in,
                              void* d_out, int out_size) {
    const float* x_edge   = (const float*)d_in[0];
    const float* node_in  = (const float*)d_in[1];
    const float* edge_vec = (const float*)d_in[2];
    const int*   sp       = (const int*)d_in[3];
    const float* dot_w    = (const float*)d_in[4];
    const float* dot_b    = (const float*)d_in[5];
    const float* w0  = (const float*)d_in[6];
    const float* b0  = (const float*)d_in[7];
    const float* w1  = (const float*)d_in[8];
    const float* b1  = (const float*)d_in[9];
    const float* w2  = (const float*)d_in[10];
    const float* b2  = (const float*)d_in[11];
    const float* g0  = (const float*)d_in[12];
    const float* bb0 = (const float*)d_in[13];
    const float* g1  = (const float*)d_in[14];
    const float* bb1 = (const float*)d_in[15];
    const float* fcw = (const float*)d_in[16];
    const float* fcb = (const float*)d_in[17];
    const float* lng = (const float*)d_in[18];
    const float* lnb = (const float*)d_in[19];
    const float* ad  = (const float*)d_in[20];
    float* out = (float*)d_out;

    k1_node<<<NN, 256>>>(node_in, dot_w, dot_b);

    size_t smem2 = (size_t)SMEM2_FLOATS * sizeof(float);
    cudaFuncSetAttribute(k2_fused, cudaFuncAttributeMaxDynamicSharedMemorySize, (int)smem2);
    k2_fused<<<NN / 2, 256, smem2>>>(x_edge, edge_vec, sp,
                                     w0, b0, w1, b1, w2, b2, g0, bb0, g1, bb1,
                                     fcw, fcb, lng, lnb, ad, out);
}

// round 6
// speedup vs baseline: 1.9125x; 1.0368x over previous
#include <cuda_runtime.h>
#include <cuda_bf16.h>
#include <math.h>
#include <stdint.h>

#define NN    8192
#define KK    32
#define EE    (NN*KK)
#define CIN   128
#define CATT  128
#define NROWS 9
#define RAD3  768

// ---- scratch ----
__device__ float g_node[(size_t)NN * NROWS * CATT];
__device__ __nv_bfloat16 g_w2h[768 * 64], g_w2l[768 * 64];
__device__ __nv_bfloat16 g_fch[256 * 768], g_fcl[256 * 768];

__device__ __forceinline__ void split_bf16(float v, __nv_bfloat16& hi, __nv_bfloat16& lo) {
    hi = __float2bfloat16(v);
    lo = __float2bfloat16(v - __bfloat162float(hi));
}

// ===================== K0: pre-split w2 / fc_w to bf16 hi/lo =================
__global__ void k0_split(const float* __restrict__ w2, const float* __restrict__ fcw) {
    int i = blockIdx.x * blockDim.x + threadIdx.x;
    if (i < 768 * 64) {
        __nv_bfloat16 h, l; split_bf16(w2[i], h, l);
        g_w2h[i] = h; g_w2l[i] = l;
    }
    if (i < 256 * 768) {
        __nv_bfloat16 h, l; split_bf16(fcw[i], h, l);
        g_fch[i] = h; g_fcl[i] = l;
    }
}

// ===================== K1 ==========
__global__ void k1_node(const float* __restrict__ node_in,
                        const float* __restrict__ dot_w,
                        const float* __restrict__ dot_b) {
    __shared__ __align__(16) float sm[NROWS * CIN];
    int n = blockIdx.x;
    const float* src = node_in + (size_t)n * NROWS * CIN;
    for (int i = threadIdx.x; i < NROWS * CIN; i += blockDim.x) sm[i] = src[i];
    __syncthreads();
    for (int idx = threadIdx.x; idx < NROWS * CATT; idx += blockDim.x) {
        int m = idx >> 7;
        int d = idx & 127;
        int l = (m == 0) ? 0 : (m < 4 ? 1 : 2);
        const float4* w = reinterpret_cast<const float4*>(dot_w + (size_t)l * CATT * CIN + (size_t)d * CIN);
        const float4* x = reinterpret_cast<const float4*>(sm + m * CIN);
        float acc = (m == 0) ? dot_b[d] : 0.f;
#pragma unroll
        for (int c4 = 0; c4 < CIN / 4; c4++) {
            float4 wv = __ldg(&w[c4]);
            float4 xv = x[c4];
            acc += wv.x * xv.x + wv.y * xv.y + wv.z * xv.z + wv.w * xv.w;
        }
        g_node[(size_t)n * NROWS * CATT + idx] = acc;
    }
}

// ===================== mma / async helpers ======================
__device__ __forceinline__ uint32_t sptr(const void* p) {
    return (uint32_t)__cvta_generic_to_shared(p);
}
__device__ __forceinline__ void ldmx4(uint32_t addr, uint32_t& r0, uint32_t& r1,
                                      uint32_t& r2, uint32_t& r3) {
    asm volatile("ldmatrix.sync.aligned.m8n8.x4.shared.b16 {%0,%1,%2,%3}, [%4];"
                 : "=r"(r0), "=r"(r1), "=r"(r2), "=r"(r3) : "r"(addr));
}
__device__ __forceinline__ void mma16816(float* c, const uint32_t* a, const uint32_t* b) {
    asm volatile("mma.sync.aligned.m16n8k16.row.col.f32.bf16.bf16.f32 "
                 "{%0,%1,%2,%3}, {%4,%5,%6,%7}, {%8,%9}, {%0,%1,%2,%3};"
                 : "+f"(c[0]), "+f"(c[1]), "+f"(c[2]), "+f"(c[3])
                 : "r"(a[0]), "r"(a[1]), "r"(a[2]), "r"(a[3]), "r"(b[0]), "r"(b[1]));
}
__device__ __forceinline__ void cpa16(void* s, const void* g) {
    asm volatile("cp.async.cg.shared.global [%0], [%1], 16;" :: "r"(sptr(s)), "l"(g));
}
__device__ __forceinline__ void cpa_commit() {
    asm volatile("cp.async.commit_group;");
}
template<int N> __device__ __forceinline__ void cpa_wait() {
    asm volatile("cp.async.wait_group %0;" :: "n"(N));
}

// ===================== K2 fused ===========
#define OFF_XS    0                        // 8448
#define OFF_WREG  8448                     // 9216: w0s | W2hi/W2lo (128x72 bf16 each)
#define OFF_W1REG 17664                    // 4608: w1s | Hhi/Hlo (64x72 bf16 each)
#define OFF_H0    22272                    // 4352: h0s | Yhi (64x136 bf16)
#define OFF_H1    26624                    // 4352: h1s | Ylo
#define OFF_SH    30976                    // 768
#define OFF_NF    31744                    // 2304
#define OFF_IDX   34048                    // 64
#define OFF_FCB   34112                    // 18432: FCW double buffer (2 x (hi+lo) x 128x72 bf16)
#define SMEM2_FLOATS 52544                 // 210176 B

__device__ __forceinline__ void ln_silu_par(float* hs, const float* __restrict__ g,
                                            const float* __restrict__ b, int tid) {
    int e = tid >> 2, p = tid & 3;
    float* row = hs + e * 68 + p * 16;
    float v[16];
    float s1 = 0.f, s2 = 0.f;
#pragma unroll
    for (int i = 0; i < 16; i++) { v[i] = row[i]; s1 += v[i]; s2 += v[i] * v[i]; }
    s1 += __shfl_xor_sync(0xffffffff, s1, 1);
    s2 += __shfl_xor_sync(0xffffffff, s2, 1);
    s1 += __shfl_xor_sync(0xffffffff, s1, 2);
    s2 += __shfl_xor_sync(0xffffffff, s2, 2);
    float mean = s1 * (1.f / 64.f);
    float var  = s2 * (1.f / 64.f) - mean * mean;
    float rs   = rsqrtf(var + 1e-5f);
#pragma unroll
    for (int i = 0; i < 16; i++) {
        float z = (v[i] - mean) * rs * __ldg(&g[p * 16 + i]) + __ldg(&b[p * 16 + i]);
        row[i] = z / (1.f + expf(-z));
    }
}

// issue FCW sub-stage (128n x 64k hi+lo) via cp.async, one commit group
__device__ __forceinline__ void issue_fcw(__nv_bfloat16* dh, __nv_bfloat16* dl,
                                          int b, int hf, int ks, int tid) {
#pragma unroll
    for (int j = 0; j < 4; j++) {
        int cid = tid + 256 * j;
        int nr = cid >> 3, kc = cid & 7;
        size_t src = (size_t)(hf * 128 + nr) * RAD3 + b * 128 + ks * 64 + kc * 8;
        cpa16(&dh[nr * 72 + kc * 8], g_fch + src);
        cpa16(&dl[nr * 72 + kc * 8], g_fcl + src);
    }
    cpa_commit();
}
// issue W2 chunk (128j x 64k hi+lo), one commit group
__device__ __forceinline__ void issue_w2(__nv_bfloat16* dh, __nv_bfloat16* dl,
                                         int b, int tid) {
#pragma unroll
    for (int j = 0; j < 4; j++) {
        int cid = tid + 256 * j;
        int nr = cid >> 3, kc = cid & 7;
        size_t src = (size_t)(b * 128 + nr) * 64 + kc * 8;
        cpa16(&dh[nr * 72 + kc * 8], g_w2h + src);
        cpa16(&dl[nr * 72 + kc * 8], g_w2l + src);
    }
    cpa_commit();
}

__device__ __forceinline__ void fc_substage(
    const __nv_bfloat16* Yhi, const __nv_bfloat16* Ylo,
    const __nv_bfloat16* Bh, const __nv_bfloat16* Bl,
    int ks, int we2, int wsub, int h_row, int h_col, int b_n, int b_k,
    float acc[8][4])
{
#pragma unroll
    for (int kk = 0; kk < 4; kk++) {
        uint32_t ah[4], al[4];
        ldmx4(sptr(&Yhi[(we2 * 16 + h_row) * 136 + ks * 64 + kk * 16 + h_col]), ah[0], ah[1], ah[2], ah[3]);
        ldmx4(sptr(&Ylo[(we2 * 16 + h_row) * 136 + ks * 64 + kk * 16 + h_col]), al[0], al[1], al[2], al[3]);
#pragma unroll
        for (int np = 0; np < 4; np++) {
            uint32_t bh[4], bl[4];
            ldmx4(sptr(&Bh[(wsub * 64 + np * 16 + b_n) * 72 + kk * 16 + b_k]), bh[0], bh[1], bh[2], bh[3]);
            ldmx4(sptr(&Bl[(wsub * 64 + np * 16 + b_n) * 72 + kk * 16 + b_k]), bl[0], bl[1], bl[2], bl[3]);
#pragma unroll
            for (int n8 = 0; n8 < 2; n8++) {
                float* c = acc[np * 2 + n8];
                mma16816(c, ah, &bh[n8 * 2]);
                mma16816(c, al, &bh[n8 * 2]);
                mma16816(c, ah, &bl[n8 * 2]);
            }
        }
    }
}

__global__ void __launch_bounds__(256, 1) k2_fused(
    const float* __restrict__ x_edge, const float* __restrict__ edge_vec,
    const int* __restrict__ sp_idx,
    const float* __restrict__ w0, const float* __restrict__ b0,
    const float* __restrict__ w1, const float* __restrict__ b1,
    const float* __restrict__ b2,
    const float* __restrict__ g0, const float* __restrict__ bb0,
    const float* __restrict__ g1, const float* __restrict__ bb1,
    const float* __restrict__ fc_b,
    const float* __restrict__ ln_g, const float* __restrict__ ln_b,
    const float* __restrict__ alpha_dot, float* __restrict__ out)
{
    extern __shared__ __align__(16) float smem[];
    float* xs    = smem + OFF_XS;
    float* wreg  = smem + OFF_WREG;
    float* w1reg = smem + OFF_W1REG;
    float* h0s   = smem + OFF_H0;
    float* h1s   = smem + OFF_H1;
    float* shs   = smem + OFF_SH;
    float* nfs   = smem + OFF_NF;
    int*   idxs  = (int*)(smem + OFF_IDX);

    __nv_bfloat16* Hhi  = (__nv_bfloat16*)w1reg;          // 64 x 72
    __nv_bfloat16* Hlo  = Hhi + 64 * 72;
    __nv_bfloat16* W2hi = (__nv_bfloat16*)wreg;           // 128 x 72
    __nv_bfloat16* W2lo = W2hi + 128 * 72;
    __nv_bfloat16* Yhi  = (__nv_bfloat16*)h0s;            // 64 x 136
    __nv_bfloat16* Ylo  = (__nv_bfloat16*)h1s;
    __nv_bfloat16* FCB  = (__nv_bfloat16*)(smem + OFF_FCB);
    // buffer i: hi at FCB + i*18432, lo at +9216

    int tid = threadIdx.x;
    int n0  = blockIdx.x * 2;
    int eg0 = blockIdx.x * 64;

    // prologue: FCW buffers are free -> start loading chunk0 sub-stages 0,1 now
    issue_fcw(FCB,          FCB + 9216,  0, 0, 0, tid);             // s0 -> buf0
    issue_fcw(FCB + 18432,  FCB + 27648, 0, 0, 1, tid);             // s1 -> buf1

    // ---- stage inputs ----
    if (tid < 64) idxs[tid] = sp_idx[eg0 + tid];
    for (int i = tid; i < 2 * NROWS * CATT; i += 256)
        nfs[i] = g_node[(size_t)n0 * NROWS * CATT + i];
    for (int i = tid; i < 64 * 128; i += 256) {
        int e = i >> 7, c = i & 127;
        xs[e * 132 + c] = x_edge[(size_t)(eg0 + e) * 128 + c];
    }
    for (int i = tid; i < 64 * 128; i += 256) {
        int o = i >> 7, c = i & 127;
        wreg[o * 132 + c] = __ldg(&w0[o * 128 + c]);
    }
    for (int i = tid; i < 64 * 64; i += 256) {
        int o = i >> 6, c = i & 63;
        w1reg[o * 68 + c] = __ldg(&w1[o * 64 + c]);
    }
    if (tid < 64) {
        const float* ev = edge_vec + (size_t)(eg0 + tid) * 3;
        float x = ev[0], y = ev[1], z = ev[2];
        float nrm = sqrtf(x * x + y * y + z * z);
        float inv = 1.f / fmaxf(nrm, 1e-12f);
        x *= inv; y *= inv; z *= inv;
        float* s = shs + tid * 12;
        const float C0 = 0.28209479177387814f;
        const float C1 = 0.4886025119029199f;
        const float C2 = 0.6307831305050401f;
        const float S3 = 1.7320508075688772f;
        s[0] = C0;
        s[1] = C1 * x; s[2] = C1 * y; s[3] = C1 * z;
        s[4] = C2 * S3 * x * z;
        s[5] = C2 * S3 * x * y;
        s[6] = C2 * (y * y - 0.5f * (x * x + z * z));
        s[7] = C2 * S3 * y * z;
        s[8] = C2 * 0.5f * S3 * (z * z - x * x);
    }
    __syncthreads();

    int tx = tid & 15;
    int ty = tid >> 4;
    int o4 = tx * 4, e4 = ty * 4;

    // ---- rad0 ----
    {
        float a[4][4];
        float4 bv = *(const float4*)&b0[o4];
#pragma unroll
        for (int i = 0; i < 4; i++) { a[i][0]=bv.x; a[i][1]=bv.y; a[i][2]=bv.z; a[i][3]=bv.w; }
#pragma unroll 4
        for (int k4 = 0; k4 < 32; k4++) {
            float4 xv[4], wv[4];
#pragma unroll
            for (int i = 0; i < 4; i++) xv[i] = *(const float4*)&xs[(e4 + i) * 132 + k4 * 4];
#pragma unroll
            for (int j = 0; j < 4; j++) wv[j] = *(const float4*)&wreg[(o4 + j) * 132 + k4 * 4];
#pragma unroll
            for (int i = 0; i < 4; i++)
#pragma unroll
                for (int j = 0; j < 4; j++)
                    a[i][j] += xv[i].x * wv[j].x + xv[i].y * wv[j].y +
                               xv[i].z * wv[j].z + xv[i].w * wv[j].w;
        }
#pragma unroll
        for (int i = 0; i < 4; i++)
            *(float4*)&h0s[(e4 + i) * 68 + o4] = make_float4(a[i][0], a[i][1], a[i][2], a[i][3]);
    }
    __syncthreads();
    // wreg now free -> start W2 chunk0 load (overlaps LN + rad1)
    issue_w2(W2hi, W2lo, 0, tid);
    ln_silu_par(h0s, g0, bb0, tid);
    __syncthreads();

    // ---- rad1 ----
    {
        float a[4][4];
        float4 bv = *(const float4*)&b1[o4];
#pragma unroll
        for (int i = 0; i < 4; i++) { a[i][0]=bv.x; a[i][1]=bv.y; a[i][2]=bv.z; a[i][3]=bv.w; }
#pragma unroll 4
        for (int k4 = 0; k4 < 16; k4++) {
            float4 xv[4], wv[4];
#pragma unroll
            for (int i = 0; i < 4; i++) xv[i] = *(const float4*)&h0s[(e4 + i) * 68 + k4 * 4];
#pragma unroll
            for (int j = 0; j < 4; j++) wv[j] = *(const float4*)&w1reg[(o4 + j) * 68 + k4 * 4];
#pragma unroll
            for (int i = 0; i < 4; i++)
#pragma unroll
                for (int j = 0; j < 4; j++)
                    a[i][j] += xv[i].x * wv[j].x + xv[i].y * wv[j].y +
                               xv[i].z * wv[j].z + xv[i].w * wv[j].w;
        }
#pragma unroll
        for (int i = 0; i < 4; i++)
            *(float4*)&h1s[(e4 + i) * 68 + o4] = make_float4(a[i][0], a[i][1], a[i][2], a[i][3]);
    }
    __syncthreads();
    ln_silu_par(h1s, g1, bb1, tid);
    __syncthreads();

    // ---- h1 -> bf16 hi/lo into Hhi/Hlo (w1reg region; h1s reads first) ----
    {
        float hv[16];
        int e = tid >> 2, p = tid & 3;
#pragma unroll
        for (int i = 0; i < 16; i++) hv[i] = h1s[e * 68 + p * 16 + i];
        __syncthreads();
#pragma unroll
        for (int i = 0; i < 16; i++) {
            __nv_bfloat16 hi, lo;
            split_bf16(hv[i], hi, lo);
            Hhi[e * 72 + p * 16 + i] = hi;
            Hlo[e * 72 + p * 16 + i] = lo;
        }
    }
    __syncthreads();

    // ---- warp roles ----
    int lane = tid & 31, warp = tid >> 5;
    int we   = warp & 3, wj = warp >> 2;
    int wsub = warp & 1, we2 = warp >> 1;
    int g = lane >> 3, r = lane & 7;
    int h_row = r + ((g & 1) << 3);
    int h_col = (g >> 1) << 3;
    int b_n   = r + ((g >> 1) << 3);
    int b_k   = (g & 1) << 3;
    int e_lo = lane >> 2, q = lane & 3;

    float acc[2][8][4];
#pragma unroll
    for (int a0 = 0; a0 < 2; a0++)
#pragma unroll
        for (int a1 = 0; a1 < 8; a1++)
#pragma unroll
            for (int a2 = 0; a2 < 4; a2++) acc[a0][a1][a2] = 0.f;

    // ---- 6 chunks ----
    // invariant at loop top: pending cp.async groups = [s0(b), W2(b), s1(b)] (order varies, all must finish)
    for (int b = 0; b < 6; b++) {
        int bn = (b < 5) ? b + 1 : 0;     // next-chunk index (dummy reload of 0 on last iter)

        // x0 chunk (64 x 128) into xs — overlaps in-flight cp.asyncs
        for (int i = tid; i < 64 * 128; i += 256) {
            int e = i >> 7, d = i & 127;
            const float* s = shs + e * 12;
            const float* src;
            if (b & 1) src = g_node + (size_t)idxs[e] * (NROWS * CATT);
            else       src = nfs + (e >> 5) * (NROWS * CATT);
            float x0;
            if      (b < 2) x0 = s[0] * src[d];
            else if (b < 4) x0 = s[1] * src[128 + d] + s[2] * src[256 + d] + s[3] * src[384 + d];
            else            x0 = s[4] * src[512 + d] + s[5] * src[640 + d] + s[6] * src[768 + d]
                               + s[7] * src[896 + d] + s[8] * src[1024 + d];
            xs[e * 132 + d] = x0;
        }
        cpa_wait<0>();          // W2(b), s0(b), s1(b) all resident
        __syncthreads();

        // w2-mma: edge_m0 [64e x 128j]; y -> Yhi/Ylo
        {
            float acc2[4][2][4];
#pragma unroll
            for (int np = 0; np < 4; np++)
#pragma unroll
                for (int n8 = 0; n8 < 2; n8++)
#pragma unroll
                    for (int c = 0; c < 4; c++) acc2[np][n8][c] = 0.f;

#pragma unroll
            for (int kk = 0; kk < 4; kk++) {
                uint32_t ah[4], al[4];
                ldmx4(sptr(&Hhi[(we * 16 + h_row) * 72 + kk * 16 + h_col]), ah[0], ah[1], ah[2], ah[3]);
                ldmx4(sptr(&Hlo[(we * 16 + h_row) * 72 + kk * 16 + h_col]), al[0], al[1], al[2], al[3]);
#pragma unroll
                for (int np = 0; np < 4; np++) {
                    uint32_t bh[4], bl[4];
                    ldmx4(sptr(&W2hi[(wj * 64 + np * 16 + b_n) * 72 + kk * 16 + b_k]), bh[0], bh[1], bh[2], bh[3]);
                    ldmx4(sptr(&W2lo[(wj * 64 + np * 16 + b_n) * 72 + kk * 16 + b_k]), bl[0], bl[1], bl[2], bl[3]);
#pragma unroll
                    for (int n8 = 0; n8 < 2; n8++) {
                        float* c = acc2[np][n8];
                        mma16816(c, ah, &bh[n8 * 2]);
                        mma16816(c, al, &bh[n8 * 2]);
                        mma16816(c, ah, &bl[n8 * 2]);
                    }
                }
            }
#pragma unroll
            for (int np = 0; np < 4; np++) {
#pragma unroll
                for (int n8 = 0; n8 < 2; n8++) {
                    int jl = wj * 64 + np * 16 + n8 * 8 + 2 * q;
                    int jgl = b * 128 + jl;
                    float b2v0 = __ldg(&b2[jgl]);
                    float b2v1 = __ldg(&b2[jgl + 1]);
#pragma unroll
                    for (int half = 0; half < 2; half++) {
                        int e = we * 16 + e_lo + half * 8;
                        float2 x0v = *(const float2*)&xs[e * 132 + jl];
                        float y0 = x0v.x * (acc2[np][n8][half * 2]     + b2v0);
                        float y1 = x0v.y * (acc2[np][n8][half * 2 + 1] + b2v1);
                        __nv_bfloat16 yh0, yl0, yh1, yl1;
                        split_bf16(y0, yh0, yl0);
                        split_bf16(y1, yh1, yl1);
                        *reinterpret_cast<__nv_bfloat162*>(&Yhi[e * 136 + jl]) = __nv_bfloat162(yh0, yh1);
                        *reinterpret_cast<__nv_bfloat162*>(&Ylo[e * 136 + jl]) = __nv_bfloat162(yl0, yl1);
                    }
                }
            }
        }
        __syncthreads();   // Y visible to all warps

        // FC s0 (hf=0, ks=0, buf0)
        fc_substage(Yhi, Ylo, FCB, FCB + 9216, 0, we2, wsub, h_row, h_col, b_n, b_k, acc[0]);
        __syncthreads();                                         // buf0 free
        issue_fcw(FCB, FCB + 9216, b, 1, 0, tid);                // s2 -> buf0  [pending: s2]

        // FC s1 (hf=0, ks=1, buf1)
        fc_substage(Yhi, Ylo, FCB + 18432, FCB + 27648, 1, we2, wsub, h_row, h_col, b_n, b_k, acc[0]);
        __syncthreads();                                         // buf1 free
        issue_fcw(FCB + 18432, FCB + 27648, b, 1, 1, tid);       // s3 -> buf1  [pending: s2, s3]

        cpa_wait<1>();                                           // s2 resident
        // FC s2 (hf=1, ks=0, buf0)
        fc_substage(Yhi, Ylo, FCB, FCB + 9216, 0, we2, wsub, h_row, h_col, b_n, b_k, acc[1]);
        __syncthreads();                                         // buf0 free
        issue_fcw(FCB, FCB + 9216, bn, 0, 0, tid);               // s0' -> buf0
        issue_w2(W2hi, W2lo, bn, tid);                           // W2'  [pending: s3, s0', W2']

        cpa_wait<2>();                                           // s3 resident
        // FC s3 (hf=1, ks=1, buf1)
        fc_substage(Yhi, Ylo, FCB + 18432, FCB + 27648, 1, we2, wsub, h_row, h_col, b_n, b_k, acc[1]);
        __syncthreads();                                         // buf1 free
        issue_fcw(FCB + 18432, FCB + 27648, bn, 0, 1, tid);      // s1'  [pending: s0', W2', s1']
    }
    cpa_wait<0>();   // drain trailing dummy loads before exit

    // ---- epilogue ----
#pragma unroll
    for (int hf = 0; hf < 2; hf++) {
#pragma unroll
        for (int half8 = 0; half8 < 2; half8++) {
            int erow = eg0 + we2 * 16 + e_lo + half8 * 8;
#pragma unroll
            for (int hd = 0; hd < 2; hd++) {
                int hg = hf * 4 + wsub * 2 + hd;
                float v[8];
#pragma unroll
                for (int tt = 0; tt < 4; tt++) {
#pragma unroll
                    for (int c = 0; c < 2; c++) {
                        int d  = tt * 8 + 2 * q + c;
                        int ng = hf * 128 + wsub * 64 + hd * 32 + d;
                        v[tt * 2 + c] = acc[hf][hd * 4 + tt][half8 * 2 + c] + __ldg(&fc_b[ng]);
                    }
                }
                float s1 = 0.f, s2 = 0.f;
#pragma unroll
                for (int j = 0; j < 8; j++) { s1 += v[j]; s2 += v[j] * v[j]; }
                s1 += __shfl_xor_sync(0xffffffff, s1, 1);
                s2 += __shfl_xor_sync(0xffffffff, s2, 1);
                s1 += __shfl_xor_sync(0xffffffff, s1, 2);
                s2 += __shfl_xor_sync(0xffffffff, s2, 2);
                float mean = s1 * (1.f / 32.f);
                float var  = s2 * (1.f / 32.f) - mean * mean;
                float rs   = rsqrtf(var + 1e-5f);
                float p = 0.f;
#pragma unroll
                for (int j = 0; j < 8; j++) {
                    int d = (j >> 1) * 8 + 2 * q + (j & 1);
                    float z = (v[j] - mean) * rs * __ldg(&ln_g[d]) + __ldg(&ln_b[d]);
                    float sg = 1.f / (1.f + expf(-z));
                    float slr = 0.6f * z + 0.4f * z * (2.f * sg - 1.f);
                    p += slr * __ldg(&alpha_dot[hg * 32 + d]);
                }
                p += __shfl_xor_sync(0xffffffff, p, 1);
                p += __shfl_xor_sync(0xffffffff, p, 2);
                if (q == 0)
                    out[(size_t)erow * 8 + hg] = p;
            }
        }
    }
}

// ===================== launch =====================
extern "C" void kernel_launch(void* const* d_in, const int* in_sizes, int n_in,
                              void* d_out, int out_size) {
    const float* x_edge   = (const float*)d_in[0];
    const float* node_in  = (const float*)d_in[1];
    const float* edge_vec = (const float*)d_in[2];
    const int*   sp       = (const int*)d_in[3];
    const float* dot_w    = (const float*)d_in[4];
    const float* dot_b    = (const float*)d_in[5];
    const float* w0  = (const float*)d_in[6];
    const float* b0  = (const float*)d_in[7];
    const float* w1  = (const float*)d_in[8];
    const float* b1  = (const float*)d_in[9];
    const float* w2  = (const float*)d_in[10];
    const float* b2  = (const float*)d_in[11];
    const float* g0  = (const float*)d_in[12];
    const float* bb0 = (const float*)d_in[13];
    const float* g1  = (const float*)d_in[14];
    const float* bb1 = (const float*)d_in[15];
    const float* fcw = (const float*)d_in[16];
    const float* fcb = (const float*)d_in[17];
    const float* lng = (const float*)d_in[18];
    const float* lnb = (const float*)d_in[19];
    const float* ad  = (const float*)d_in[20];
    float* out = (float*)d_out;

    k0_split<<<768, 256>>>(w2, fcw);
    k1_node<<<NN, 256>>>(node_in, dot_w, dot_b);

    size_t smem2 = (size_t)SMEM2_FLOATS * sizeof(float);
    cudaFuncSetAttribute(k2_fused, cudaFuncAttributeMaxDynamicSharedMemorySize, (int)smem2);
    k2_fused<<<NN / 2, 256, smem2>>>(x_edge, edge_vec, sp,
                                     w0, b0, w1, b1, b2, g0, bb0, g1, bb1,
                                     fcb, lng, lnb, ad, out);
}